// round 11
// baseline (speedup 1.0000x reference)
#include <cuda_runtime.h>
#include <cuda_bf16.h>
#include <cstdint>

#define Bq 2048
#define Tq 128
#define Nq (Bq*Tq)

// ---------------- scratch (no allocations allowed) ----------------
__device__ float g_air[(size_t)Nq * 32];
__device__ float g_m1 [(size_t)Nq * 32];
__device__ float g_m2 [(size_t)Nq * 32];
__device__ float g_fusion[(size_t)Nq * 64];
// prepacked bf16 hi/lo MLP weights, row-major [n][k]
__device__ __nv_bfloat16 g_W0h[256 * 64];
__device__ __nv_bfloat16 g_W0l[256 * 64];
__device__ __nv_bfloat16 g_W1h[256 * 256];
__device__ __nv_bfloat16 g_W1l[256 * 256];
// GRU tensor-core prepack: B-fragments, biases, X A-fragments
__device__ uint2  g_gB[2 * 36 * 2 * 32];            // [ty][pair][part][lane] -> 2 regs
__device__ float  g_gBias[2 * 128];
__device__ uint4  g_gX[(size_t)384 * 128 * 32 * 2]; // [(group*128+t)*32+lane]*2+part

__device__ __forceinline__ float tanhap(float x) {
    float y;
    asm("tanh.approx.f32 %0, %1;" : "=f"(y) : "f"(x));
    return y;
}
__device__ __forceinline__ float fsig(float x) {           // sigmoid via tanh
    return fmaf(0.5f, tanhap(0.5f * x), 0.5f);
}

// packed 2xfp32 FMA
union F2U { float2 f; unsigned long long u; };
__device__ __forceinline__ float2 ffma2(float2 a, float2 b, float2 c) {
    F2U A, B, C, D;
    A.f = a; B.f = b; C.f = c;
    asm("fma.rn.f32x2 %0, %1, %2, %3;" : "=l"(D.u) : "l"(A.u), "l"(B.u), "l"(C.u));
    return D.f;
}
__device__ __forceinline__ float2 dot4_2(float4 a, float4 b, float2 acc) {
    acc = ffma2(make_float2(a.x, a.y), make_float2(b.x, b.y), acc);
    acc = ffma2(make_float2(a.z, a.w), make_float2(b.z, b.w), acc);
    return acc;
}

// ---------------- mma.sync / cp.async helpers ----------------
__device__ __forceinline__ uint32_t smem_u32(const void* p) {
    uint32_t a;
    asm("{ .reg .u64 t; cvta.to.shared.u64 t, %1; cvt.u32.u64 %0, t; }" : "=r"(a) : "l"(p));
    return a;
}
__device__ __forceinline__ void ldsm4(uint32_t* a, uint32_t addr) {
    asm volatile("ldmatrix.sync.aligned.m8n8.x4.shared.b16 {%0,%1,%2,%3}, [%4];"
        : "=r"(a[0]), "=r"(a[1]), "=r"(a[2]), "=r"(a[3]) : "r"(addr));
}
__device__ __forceinline__ void ldsm2(uint32_t* b, uint32_t addr) {
    asm volatile("ldmatrix.sync.aligned.m8n8.x2.shared.b16 {%0,%1}, [%2];"
        : "=r"(b[0]), "=r"(b[1]) : "r"(addr));
}
__device__ __forceinline__ void mma16816(float* c, const uint32_t* a, const uint32_t* b) {
    asm volatile("mma.sync.aligned.m16n8k16.row.col.f32.bf16.bf16.f32 "
        "{%0,%1,%2,%3}, {%4,%5,%6,%7}, {%8,%9}, {%0,%1,%2,%3};"
        : "+f"(c[0]), "+f"(c[1]), "+f"(c[2]), "+f"(c[3])
        : "r"(a[0]), "r"(a[1]), "r"(a[2]), "r"(a[3]), "r"(b[0]), "r"(b[1]));
}
__device__ __forceinline__ void cpa16(uint32_t dst, const void* src) {
    asm volatile("cp.async.cg.shared.global [%0], [%1], 16;" :: "r"(dst), "l"(src));
}
#define CPA_COMMIT() asm volatile("cp.async.commit_group;" ::: "memory")
#define SWZ(x) ((x) ^ (((x) >> 3) & 0x70))

__device__ __forceinline__ __nv_bfloat162 split_hi(float a, float b) {
    __nv_bfloat162 h; h.x = __float2bfloat16(a); h.y = __float2bfloat16(b); return h;
}
__device__ __forceinline__ __nv_bfloat162 split_lo(float a, float b, __nv_bfloat162 h) {
    __nv_bfloat162 l;
    l.x = __float2bfloat16(a - __bfloat162float(h.x));
    l.y = __float2bfloat16(b - __bfloat162float(h.y));
    return l;
}
__device__ __forceinline__ uint32_t bf2u(__nv_bfloat162 v) {
    return *reinterpret_cast<uint32_t*>(&v);
}

// GRU tile-pair tables, kt-OUTER ordering so consecutive MMAs hit different
// accumulators. nt 0-7: r,z; nt 8-11: hn (h only); nt 12-15: xn (x only).
#define GRU_PNT {0,1,2,3,4,5,6,7,8,9,10,11, 0,1,2,3,4,5,6,7,8,9,10,11, 0,1,2,3,4,5,6,7,12,13,14,15}
#define GRU_PKT {0,0,0,0,0,0,0,0,0,0,0,0,  1,1,1,1,1,1,1,1,1,1,1,1,   2,2,2,2,2,2,2,2,2,2,2,2}

// ================= MLP weight prepack =================
__global__ void k_pack(const float* __restrict__ W0, const float* __restrict__ W1) {
    int i = blockIdx.x * 256 + threadIdx.x;
    if (i < 16384) {
        float w = W0[i];
        __nv_bfloat16 h = __float2bfloat16(w);
        g_W0h[i] = h;
        g_W0l[i] = __float2bfloat16(w - __bfloat162float(h));
    } else if (i < 16384 + 65536) {
        int j = i - 16384;
        float w = W1[j];
        __nv_bfloat16 h = __float2bfloat16(w);
        g_W1h[j] = h;
        g_W1l[j] = __float2bfloat16(w - __bfloat162float(h));
    }
}

// ================= GRU weight/bias prepack =================
__device__ __forceinline__ float gru_bval(
    int k, int n, const float* Whh, const float* Wih, const float* encW, int KIN)
{
    int blk = n >> 5, j = n & 31;
    if (k < 32) {
        if (blk == 3) return 0.f;
        return Whh[(blk * 32 + j) * 32 + k];
    }
    int f = k - 32;
    if (f >= KIN || blk == 2) return 0.f;
    int row = (blk == 3) ? 64 + j : blk * 32 + j;
    float s = 0.f;
    #pragma unroll
    for (int m = 0; m < 32; m++) s = fmaf(Wih[row * 32 + m], encW[m * KIN + f], s);
    return s;
}

__global__ void k_packg_w(
    const float* __restrict__ aWih, const float* __restrict__ aWhh,
    const float* __restrict__ abih, const float* __restrict__ abhh,
    const float* __restrict__ eAW,  const float* __restrict__ eAb,
    const float* __restrict__ mWih, const float* __restrict__ mWhh,
    const float* __restrict__ mbih, const float* __restrict__ mbhh,
    const float* __restrict__ eMW,  const float* __restrict__ eMb)
{
    const int PNT[36] = GRU_PNT;
    const int PKT[36] = GRU_PKT;
    int tid = blockIdx.x * 256 + threadIdx.x;
    if (tid < 2304) {
        int lane = tid & 31;
        int p = (tid >> 5) % 36;
        int ty = tid / (36 * 32);
        const float* Whh = ty ? mWhh : aWhh;
        const float* Wih = ty ? mWih : aWih;
        const float* eW  = ty ? eMW  : eAW;
        int KIN = ty ? 4 : 7;
        int g = lane >> 2, tq = lane & 3;
        int n = PNT[p] * 8 + g;
        uint32_t rh[2], rl[2];
        #pragma unroll
        for (int r = 0; r < 2; r++) {
            int k0 = PKT[p] * 16 + tq * 2 + r * 8;
            float v0 = gru_bval(k0,     n, Whh, Wih, eW, KIN);
            float v1 = gru_bval(k0 + 1, n, Whh, Wih, eW, KIN);
            __nv_bfloat162 hh = split_hi(v0, v1);
            __nv_bfloat162 ll = split_lo(v0, v1, hh);
            rh[r] = bf2u(hh); rl[r] = bf2u(ll);
        }
        int base = (ty * 72 + p * 2) * 32 + lane;
        g_gB[base]      = make_uint2(rh[0], rh[1]);
        g_gB[base + 32] = make_uint2(rl[0], rl[1]);
    } else if (tid < 2304 + 256) {
        int u = tid - 2304;
        int ty = u >> 7, n = u & 127;
        const float* Wih = ty ? mWih : aWih;
        const float* bih = ty ? mbih : abih;
        const float* bhh = ty ? mbhh : abhh;
        const float* eB  = ty ? eMb  : eAb;
        int blk = n >> 5, j = n & 31;
        float b;
        if (blk == 2) {
            b = bhh[64 + j];
        } else {
            int row = (blk == 3) ? 64 + j : blk * 32 + j;
            float bc = bih[row];
            #pragma unroll
            for (int m = 0; m < 32; m++) bc = fmaf(Wih[row * 32 + m], eB[m], bc);
            b = (blk < 2) ? bc + bhh[row] : bc;
        }
        g_gBias[ty * 128 + n] = b;
    }
}

// X A-fragment prepack: per (group, t, lane) 4 hi + 4 lo regs.
__global__ void k_packg_x(const float* __restrict__ obs) {
    int tid = blockIdx.x * 256 + threadIdx.x;
    int lane = tid & 31;
    int s = tid >> 5;
    int t = s & 127;
    int gr = s >> 7;
    int g = lane >> 2, tq = lane & 3;

    int KIN, xoff;
    int b0;
    if (gr < 128) { KIN = 7; xoff = 8; b0 = gr * 16; }
    else {
        int gi = gr - 128;
        KIN = 4;
        xoff = (gi < 128) ? 0 : 4;
        b0 = (gi < 128) ? gi * 16 : (gi - 128) * 16;
    }
    uint32_t hr[4], lr[4];
    #pragma unroll
    for (int r = 0; r < 4; r++) {
        int row = g + 8 * (r & 1);
        int k0 = tq * 2 + (r >> 1) * 8;
        float v0 = 0.f, v1 = 0.f;
        if (k0 < KIN)
            v0 = obs[(size_t)(b0 + row) * Tq * 15 + t * 15 + xoff + k0];
        if (k0 + 1 < KIN)
            v1 = obs[(size_t)(b0 + row) * Tq * 15 + t * 15 + xoff + k0 + 1];
        __nv_bfloat162 hh = split_hi(v0, v1);
        __nv_bfloat162 ll = split_lo(v0, v1, hh);
        hr[r] = bf2u(hh); lr[r] = bf2u(ll);
    }
    size_t idx = ((size_t)(gr * 128 + t) * 32 + lane) * 2;
    g_gX[idx]     = make_uint4(hr[0], hr[1], hr[2], hr[3]);
    g_gX[idx + 1] = make_uint4(lr[0], lr[1], lr[2], lr[3]);
}

// ====== GRU: tensor-core recurrence, 4 warps/CTA -> 4 SMSPs, 1 group/warp ==
__global__ void __launch_bounds__(128) k_gru_tc(
    const float* __restrict__ rnn, float* __restrict__ next_h)
{
    const int PNT[36] = GRU_PNT;
    const int PKT[36] = GRU_PKT;
    int lane = threadIdx.x & 31;
    int wid = threadIdx.x >> 5;
    int w = blockIdx.x * 4 + wid;                // 0..383, one group per warp
    int g = lane >> 2, tq = lane & 3;

    int ty; float* featb; int ib; bool is_air = (w < 128);
    if (is_air) { ty = 0; featb = g_air; ib = w * 16; }
    else {
        ty = 1;
        int gi = w - 128;
        if (gi < 128) { featb = g_m1; ib = gi * 16; }
        else          { featb = g_m2; ib = (gi - 128) * 16; }
    }
    int gi = w - 128;

    float hv[4][4];
    #pragma unroll
    for (int nt = 0; nt < 4; nt++) {
        int col = nt * 8 + 2 * tq;
        #pragma unroll
        for (int rh = 0; rh < 2; rh++) {
            int row = g + 8 * rh;
            const float* src;
            if (is_air) src = rnn + (size_t)(w * 16 + row) * 96 + col;
            else {
                int i = gi * 16 + row;
                src = rnn + (size_t)(i >> 1) * 96 + 32 + 32 * (i & 1) + col;
            }
            float2 v = *(const float2*)src;
            hv[nt][rh * 2]     = v.x;
            hv[nt][rh * 2 + 1] = v.y;
        }
    }
    float bias[16][2];
    #pragma unroll
    for (int nt = 0; nt < 16; nt++) {
        float2 v = *(const float2*)(g_gBias + ty * 128 + nt * 8 + 2 * tq);
        bias[nt][0] = v.x; bias[nt][1] = v.y;
    }
    uint32_t Ah[2][4], Al[2][4];
    #pragma unroll
    for (int nt = 0; nt < 4; nt++) {
        int kt = nt >> 1;
        __nv_bfloat162 h01 = split_hi(hv[nt][0], hv[nt][1]);
        __nv_bfloat162 l01 = split_lo(hv[nt][0], hv[nt][1], h01);
        __nv_bfloat162 h23 = split_hi(hv[nt][2], hv[nt][3]);
        __nv_bfloat162 l23 = split_lo(hv[nt][2], hv[nt][3], h23);
        int o = (nt & 1) ? 2 : 0;
        Ah[kt][o] = bf2u(h01); Ah[kt][o + 1] = bf2u(h23);
        Al[kt][o] = bf2u(l01); Al[kt][o + 1] = bf2u(l23);
    }

    const uint2* gBb = g_gB + ty * 72 * 32 + lane;
    const uint4* gXb = g_gX + ((size_t)w * 128) * 32 * 2 + lane * 2;
    float* fr0 = featb + (size_t)(ib + g)     * Tq * 32 + 2 * tq;
    float* fr1 = featb + (size_t)(ib + g + 8) * Tq * 32 + 2 * tq;

    uint4 xh_cur = gXb[0], xl_cur = gXb[1];

    #pragma unroll 1
    for (int t = 0; t < Tq; t++) {
        int tn = (t + 1 < Tq) ? t + 1 : t;
        uint4 xh_nxt = gXb[(size_t)tn * 64];
        uint4 xl_nxt = gXb[(size_t)tn * 64 + 1];

        uint32_t Xh[4] = {xh_cur.x, xh_cur.y, xh_cur.z, xh_cur.w};
        uint32_t Xl[4] = {xl_cur.x, xl_cur.y, xl_cur.z, xl_cur.w};
        float C[16][4];
        #pragma unroll
        for (int nt = 0; nt < 16; nt++) {
            C[nt][0] = bias[nt][0]; C[nt][1] = bias[nt][1];
            C[nt][2] = bias[nt][0]; C[nt][3] = bias[nt][1];
        }
        #pragma unroll
        for (int p = 0; p < 36; p++) {
            int nt = PNT[p], kt = PKT[p];
            uint2 bh = gBb[(p * 2) * 32];
            uint2 bl = gBb[(p * 2 + 1) * 32];
            const uint32_t* ah = (kt == 2) ? Xh : Ah[kt];
            const uint32_t* al = (kt == 2) ? Xl : Al[kt];
            mma16816(C[nt], ah, (const uint32_t*)&bh);
            mma16816(C[nt], ah, (const uint32_t*)&bl);
            mma16816(C[nt], al, (const uint32_t*)&bh);
        }
        #pragma unroll
        for (int nt = 0; nt < 4; nt++) {
            #pragma unroll
            for (int j = 0; j < 4; j++) {
                float r = fsig(C[nt][j]);
                float z = fsig(C[nt + 4][j]);
                float n = tanhap(fmaf(r, C[nt + 8][j], C[nt + 12][j]));
                hv[nt][j] = n + z * (hv[nt][j] - n);
            }
            *(float2*)(fr0 + (size_t)t * 32 + nt * 8) = make_float2(hv[nt][0], hv[nt][1]);
            *(float2*)(fr1 + (size_t)t * 32 + nt * 8) = make_float2(hv[nt][2], hv[nt][3]);
            int kt = nt >> 1;
            __nv_bfloat162 h01 = split_hi(hv[nt][0], hv[nt][1]);
            __nv_bfloat162 l01 = split_lo(hv[nt][0], hv[nt][1], h01);
            __nv_bfloat162 h23 = split_hi(hv[nt][2], hv[nt][3]);
            __nv_bfloat162 l23 = split_lo(hv[nt][2], hv[nt][3], h23);
            int o = (nt & 1) ? 2 : 0;
            Ah[kt][o] = bf2u(h01); Ah[kt][o + 1] = bf2u(h23);
            Al[kt][o] = bf2u(l01); Al[kt][o + 1] = bf2u(l23);
        }
        xh_cur = xh_nxt; xl_cur = xl_nxt;
    }
    #pragma unroll
    for (int nt = 0; nt < 4; nt++) {
        int col = nt * 8 + 2 * tq;
        #pragma unroll
        for (int rh = 0; rh < 2; rh++) {
            int row = g + 8 * rh;
            float2 v = make_float2(hv[nt][rh * 2], hv[nt][rh * 2 + 1]);
            float* dst;
            if (is_air) dst = next_h + (size_t)(w * 16 + row) * 96 + col;
            else {
                int i = gi * 16 + row;
                dst = next_h + (size_t)(i >> 1) * 96 + 32 + 32 * (i & 1) + col;
            }
            *(float2*)dst = v;
        }
    }
}

// ================= attention + fusion (unchanged) =================
__global__ void __launch_bounds__(256) k_attn(
    const float* __restrict__ obs,
    const float* __restrict__ Win, const float* __restrict__ bin,
    const float* __restrict__ Wout, const float* __restrict__ bout)
{
    __shared__ float Ws[96 * 32];
    __shared__ float Wo[32 * 32];
    __shared__ float bs[96], bo[32];
    int t = threadIdx.x;
    for (int i = t; i < 96 * 32; i += 256) Ws[i] = Win[i];
    for (int i = t; i < 32 * 32; i += 256) Wo[i] = Wout[i];
    if (t < 96) bs[t] = bin[t];
    if (t < 32) bo[t] = bout[t];
    __syncthreads();

    int warp = blockIdx.x * 8 + (t >> 5);
    int la = t & 31;
    int n = warp * 32 + la;

    float4 A[8], M1[8], M2[8];
    const float4* ap = (const float4*)(g_air + (size_t)n * 32);
    const float4* p1 = (const float4*)(g_m1 + (size_t)n * 32);
    const float4* p2 = (const float4*)(g_m2 + (size_t)n * 32);
    #pragma unroll
    for (int i = 0; i < 8; i++) { A[i] = ap[i]; M1[i] = p1[i]; M2[i] = p2[i]; }

    const float* op = obs + (size_t)n * 15;
    float o0=op[0],o1=op[1],o2=op[2],o3=op[3],o4=op[4],o5=op[5],o6=op[6],o7=op[7];
    const float T1 = 1.001e-5f, T0 = 1e-8f;
    bool mk0 = (fabsf(o0-1.f)<=T1) && (fabsf(o1)<=T0) && (fabsf(o2-1.f)<=T1) && (fabsf(o3)<=T0);
    bool mk1 = (fabsf(o4-1.f)<=T1) && (fabsf(o5)<=T0) && (fabsf(o6-1.f)<=T1) && (fabsf(o7)<=T0);

    float q[32];
    #pragma unroll
    for (int c = 0; c < 32; c++) {
        float2 a = make_float2(bs[c], 0.f);
        const float4* w = (const float4*)(Ws + c * 32);
        #pragma unroll
        for (int k = 0; k < 8; k++) a = dot4_2(A[k], w[k], a);
        q[c] = a.x + a.y;
    }
    float s1[2] = {0.f, 0.f}, s2[2] = {0.f, 0.f};
    #pragma unroll
    for (int c = 0; c < 32; c++) {
        const float4* w = (const float4*)(Ws + (32 + c) * 32);
        float2 k1 = make_float2(bs[32 + c], 0.f), k2 = make_float2(0.f, 0.f);
        #pragma unroll
        for (int k = 0; k < 8; k++) { k1 = dot4_2(M1[k], w[k], k1); k2 = dot4_2(M2[k], w[k], k2); }
        int hh = c >> 4;
        s1[hh] = fmaf(q[c], k1.x + k1.y, s1[hh]);
        s2[hh] = fmaf(q[c], k2.x + k2.y + bs[32 + c], s2[hh]);
    }
    float w1[2], w2[2];
    #pragma unroll
    for (int hh = 0; hh < 2; hh++) {
        float a = s1[hh] * 0.25f + (mk0 ? -1e9f : 0.f);
        float b = s2[hh] * 0.25f + (mk1 ? -1e9f : 0.f);
        float m = fmaxf(a, b);
        float e1 = __expf(a - m), e2 = __expf(b - m);
        float inv = __fdividef(1.0f, e1 + e2);
        w1[hh] = e1 * inv; w2[hh] = e2 * inv;
    }
    float ctx[32];
    #pragma unroll
    for (int c = 0; c < 32; c++) {
        const float4* w = (const float4*)(Ws + (64 + c) * 32);
        float2 v1 = make_float2(bs[64 + c], 0.f), v2 = make_float2(0.f, 0.f);
        #pragma unroll
        for (int k = 0; k < 8; k++) { v1 = dot4_2(M1[k], w[k], v1); v2 = dot4_2(M2[k], w[k], v2); }
        int hh = c >> 4;
        ctx[c] = w1[hh] * (v1.x + v1.y) + w2[hh] * (v2.x + v2.y + bs[64 + c]);
    }
    bool allm = mk0 && mk1;
    float at[32];
    #pragma unroll
    for (int o = 0; o < 32; o++) {
        float2 a = make_float2(bo[o], 0.f);
        const float4* w = (const float4*)(Wo + o * 32);
        #pragma unroll
        for (int c4 = 0; c4 < 8; c4++) {
            float4 cv = make_float4(ctx[4*c4], ctx[4*c4+1], ctx[4*c4+2], ctx[4*c4+3]);
            a = dot4_2(cv, w[c4], a);
        }
        at[o] = allm ? 0.0f : (a.x + a.y);
    }
    float4* fr = (float4*)(g_fusion + (size_t)n * 64);
    #pragma unroll
    for (int i = 0; i < 8; i++) fr[i] = A[i];
    #pragma unroll
    for (int i = 0; i < 8; i++)
        fr[8 + i] = make_float4(at[4*i], at[4*i+1], at[4*i+2], at[4*i+3]);
}

// ======= HMMA MLP: M=64/CTA, 2 CTAs/SM (unchanged) =======
#define SM_B0  0
#define SM_B1  1024
#define SM_OW  2048
#define SM_A1H 3072
#define SM_A1L 36864
#define SM_WB  70656
#define SM_RED 70656
#define SM_TOT 111616
#define SM_A0H 3072
#define SM_A0L 11264
#define SM_W0H 19456
#define SM_W0L 52224
#define PA1 528
#define PW1 80

__global__ void __launch_bounds__(256, 2) k_mlp_h(
    const float* __restrict__ b0, const float* __restrict__ b1,
    const float* __restrict__ oW, const float* __restrict__ ob,
    float* __restrict__ val)
{
    extern __shared__ char smem[];
    uint32_t smb = smem_u32(smem);
    int tid = threadIdx.x, wid = tid >> 5, lane = tid & 31;
    int g = lane >> 2, tq = lane & 3;
    int row0 = blockIdx.x * 64;
    int n0w = wid * 32;

    float* b0s = (float*)(smem + SM_B0);
    float* b1s = (float*)(smem + SM_B1);
    float* ows = (float*)(smem + SM_OW);
    b0s[tid] = b0[tid]; b1s[tid] = b1[tid]; ows[tid] = oW[tid];

    int aro = lane & 15;
    int aco = (lane >> 1) & 8;
    int bro = lane & 7;
    int bco = lane & 8;

    #pragma unroll
    for (int q = 0; q < 16; q++) {
        int id = tid + 256 * q;
        int part = id >> 11;
        int u = id & 2047;
        int nn = u >> 3, j = u & 7;
        uint32_t dst = smb + (part ? SM_W0L : SM_W0H) + SWZ((uint32_t)(nn * 128 + j * 16));
        const __nv_bfloat16* src = (part ? g_W0l : g_W0h) + nn * 64 + j * 8;
        cpa16(dst, src);
    }
    CPA_COMMIT();
    {
        const float4* Fg = (const float4*)g_fusion + (size_t)row0 * 16;
        #pragma unroll
        for (int q = 0; q < 4; q++) {
            int id = tid + 256 * q;
            int r = id >> 4, c4 = id & 15;
            float4 v = Fg[id];
            __nv_bfloat162 h0 = split_hi(v.x, v.y), l0 = split_lo(v.x, v.y, h0);
            __nv_bfloat162 h1 = split_hi(v.z, v.w), l1 = split_lo(v.z, v.w, h1);
            uint32_t o0 = SWZ((uint32_t)(r * 128 + c4 * 8));
            uint32_t o1 = SWZ((uint32_t)(r * 128 + c4 * 8 + 4));
            *(__nv_bfloat162*)(smem + SM_A0H + o0) = h0;
            *(__nv_bfloat162*)(smem + SM_A0H + o1) = h1;
            *(__nv_bfloat162*)(smem + SM_A0L + o0) = l0;
            *(__nv_bfloat162*)(smem + SM_A0L + o1) = l1;
        }
    }
    asm volatile("cp.async.wait_group 0;" ::: "memory");
    __syncthreads();

    float acc[4][4][4];
    #pragma unroll
    for (int m = 0; m < 4; m++)
        #pragma unroll
        for (int nt = 0; nt < 4; nt++)
            #pragma unroll
            for (int r = 0; r < 4; r++) acc[m][nt][r] = 0.f;
    #pragma unroll 1
    for (int k16 = 0; k16 < 4; k16++) {
        int kc = k16 * 16;
        uint32_t bh[4][2], bl[4][2];
        #pragma unroll
        for (int nt = 0; nt < 4; nt++) {
            uint32_t ba = SWZ((uint32_t)((n0w + 8 * nt + bro) * 128 + (kc + bco) * 2));
            ldsm2(bh[nt], smb + SM_W0H + ba);
            ldsm2(bl[nt], smb + SM_W0L + ba);
        }
        #pragma unroll
        for (int m = 0; m < 4; m++) {
            uint32_t ah[4], al[4];
            uint32_t aa = SWZ((uint32_t)((m * 16 + aro) * 128 + (kc + aco) * 2));
            ldsm4(ah, smb + SM_A0H + aa);
            ldsm4(al, smb + SM_A0L + aa);
            #pragma unroll
            for (int nt = 0; nt < 4; nt++) {
                mma16816(acc[m][nt], ah, bh[nt]);
                mma16816(acc[m][nt], ah, bl[nt]);
                mma16816(acc[m][nt], al, bh[nt]);
            }
        }
    }
    __syncthreads();

    #pragma unroll
    for (int q = 0; q < 8; q++) {
        int id = tid + 256 * q;
        int part = id >> 10;
        int u = id & 1023;
        int r = u >> 2, j = u & 3;
        const __nv_bfloat16* src = (part ? g_W1l : g_W1h) + r * 256 + j * 8;
        cpa16(smb + SM_WB + part * 20480 + r * PW1 + j * 16, src);
    }
    CPA_COMMIT();

    #pragma unroll
    for (int m = 0; m < 4; m++)
        #pragma unroll
        for (int nt = 0; nt < 4; nt++) {
            int c0 = n0w + 8 * nt + 2 * tq;
            float v0 = acc[m][nt][0] + b0s[c0];
            float v1 = acc[m][nt][1] + b0s[c0 + 1];
            float v2 = acc[m][nt][2] + b0s[c0];
            float v3 = acc[m][nt][3] + b0s[c0 + 1];
            v0 = v0 > 0.f ? v0 : 0.01f * v0;
            v1 = v1 > 0.f ? v1 : 0.01f * v1;
            v2 = v2 > 0.f ? v2 : 0.01f * v2;
            v3 = v3 > 0.f ? v3 : 0.01f * v3;
            int r0 = 16 * m + g, r1 = r0 + 8;
            __nv_bfloat162 h01 = split_hi(v0, v1), l01 = split_lo(v0, v1, h01);
            __nv_bfloat162 h23 = split_hi(v2, v3), l23 = split_lo(v2, v3, h23);
            *(__nv_bfloat162*)(smem + SM_A1H + r0 * PA1 + c0 * 2) = h01;
            *(__nv_bfloat162*)(smem + SM_A1L + r0 * PA1 + c0 * 2) = l01;
            *(__nv_bfloat162*)(smem + SM_A1H + r1 * PA1 + c0 * 2) = h23;
            *(__nv_bfloat162*)(smem + SM_A1L + r1 * PA1 + c0 * 2) = l23;
        }

    float a2[4][4][4];
    #pragma unroll
    for (int m = 0; m < 4; m++)
        #pragma unroll
        for (int nt = 0; nt < 4; nt++)
            #pragma unroll
            for (int r = 0; r < 4; r++) a2[m][nt][r] = 0.f;
    #pragma unroll 1
    for (int c = 0; c < 8; c++) {
        asm volatile("cp.async.wait_group 0;" ::: "memory");
        __syncthreads();
        uint32_t wb = smb + SM_WB;
        uint32_t bh0[4][2], bl0[4][2], bh1[4][2], bl1[4][2];
        #pragma unroll
        for (int nt = 0; nt < 4; nt++) {
            uint32_t ba0 = (uint32_t)((n0w + 8 * nt + bro) * PW1 + (bco) * 2);
            uint32_t ba1 = ba0 + 32;
            ldsm2(bh0[nt], wb + ba0);
            ldsm2(bl0[nt], wb + 20480 + ba0);
            ldsm2(bh1[nt], wb + ba1);
            ldsm2(bl1[nt], wb + 20480 + ba1);
        }
        __syncthreads();
        if (c + 1 < 8) {
            #pragma unroll
            for (int q = 0; q < 8; q++) {
                int id = tid + 256 * q;
                int part = id >> 10;
                int u = id & 1023;
                int r = u >> 2, j = u & 3;
                const __nv_bfloat16* src = (part ? g_W1l : g_W1h) + r * 256 + (c + 1) * 32 + j * 8;
                cpa16(smb + SM_WB + part * 20480 + r * PW1 + j * 16, src);
            }
            CPA_COMMIT();
        }
        #pragma unroll
        for (int m = 0; m < 4; m++) {
            uint32_t ah[4], al[4];
            uint32_t aa = (uint32_t)((m * 16 + aro) * PA1 + (c * 32 + aco) * 2);
            ldsm4(ah, smb + SM_A1H + aa);
            ldsm4(al, smb + SM_A1L + aa);
            #pragma unroll
            for (int nt = 0; nt < 4; nt++) {
                mma16816(a2[m][nt], ah, bh0[nt]);
                mma16816(a2[m][nt], ah, bl0[nt]);
                mma16816(a2[m][nt], al, bh0[nt]);
            }
            uint32_t aa1 = aa + 32;
            ldsm4(ah, smb + SM_A1H + aa1);
            ldsm4(al, smb + SM_A1L + aa1);
            #pragma unroll
            for (int nt = 0; nt < 4; nt++) {
                mma16816(a2[m][nt], ah, bh1[nt]);
                mma16816(a2[m][nt], ah, bl1[nt]);
                mma16816(a2[m][nt], al, bh1[nt]);
            }
        }
    }

    float* red = (float*)(smem + SM_RED);
    float p[4][2];
    #pragma unroll
    for (int m = 0; m < 4; m++) { p[m][0] = 0.f; p[m][1] = 0.f; }
    #pragma unroll
    for (int m = 0; m < 4; m++)
        #pragma unroll
        for (int nt = 0; nt < 4; nt++) {
            int c0 = n0w + 8 * nt + 2 * tq;
            float w0v = ows[c0], w1v = ows[c0 + 1];
            float bb0 = b1s[c0], bb1 = b1s[c0 + 1];
            float v0 = a2[m][nt][0] + bb0;
            float v1 = a2[m][nt][1] + bb1;
            float v2 = a2[m][nt][2] + bb0;
            float v3 = a2[m][nt][3] + bb1;
            v0 = v0 > 0.f ? v0 : 0.01f * v0;
            v1 = v1 > 0.f ? v1 : 0.01f * v1;
            v2 = v2 > 0.f ? v2 : 0.01f * v2;
            v3 = v3 > 0.f ? v3 : 0.01f * v3;
            p[m][0] = fmaf(v0, w0v, p[m][0]);
            p[m][0] = fmaf(v1, w1v, p[m][0]);
            p[m][1] = fmaf(v2, w0v, p[m][1]);
            p[m][1] = fmaf(v3, w1v, p[m][1]);
        }
    #pragma unroll
    for (int off = 1; off <= 2; off <<= 1)
        #pragma unroll
        for (int m = 0; m < 4; m++) {
            p[m][0] += __shfl_xor_sync(0xffffffffu, p[m][0], off);
            p[m][1] += __shfl_xor_sync(0xffffffffu, p[m][1], off);
        }
    if (tq == 0) {
        #pragma unroll
        for (int m = 0; m < 4; m++) {
            red[wid * 64 + 16 * m + g]     = p[m][0];
            red[wid * 64 + 16 * m + g + 8] = p[m][1];
        }
    }
    __syncthreads();
    if (tid < 64) {
        float s = __ldg(ob);
        #pragma unroll
        for (int w8 = 0; w8 < 8; w8++) s += red[w8 * 64 + tid];
        val[row0 + tid] = s;
    }
}

extern "C" void kernel_launch(void* const* d_in, const int* in_sizes, int n_in,
                              void* d_out, int out_size) {
    const float* obs   = (const float*)d_in[0];
    const float* rnn   = (const float*)d_in[1];
    const float* eAW   = (const float*)d_in[2];
    const float* eAb   = (const float*)d_in[3];
    const float* eMW   = (const float*)d_in[4];
    const float* eMb   = (const float*)d_in[5];
    const float* aWih  = (const float*)d_in[6];
    const float* aWhh  = (const float*)d_in[7];
    const float* abih  = (const float*)d_in[8];
    const float* abhh  = (const float*)d_in[9];
    const float* mWih  = (const float*)d_in[10];
    const float* mWhh  = (const float*)d_in[11];
    const float* mbih  = (const float*)d_in[12];
    const float* mbhh  = (const float*)d_in[13];
    const float* Win   = (const float*)d_in[14];
    const float* bin   = (const float*)d_in[15];
    const float* Wout  = (const float*)d_in[16];
    const float* bout  = (const float*)d_in[17];
    const float* W0    = (const float*)d_in[18];
    const float* b0    = (const float*)d_in[19];
    const float* W1    = (const float*)d_in[20];
    const float* b1    = (const float*)d_in[21];
    const float* oW    = (const float*)d_in[22];
    const float* ob    = (const float*)d_in[23];

    float* out_val = (float*)d_out;
    float* out_h   = (float*)d_out + Nq;

    k_pack<<<320, 256>>>(W0, W1);
    k_packg_w<<<10, 256>>>(aWih, aWhh, abih, abhh, eAW, eAb,
                           mWih, mWhh, mbih, mbhh, eMW, eMb);
    k_packg_x<<<6144, 256>>>(obs);
    k_gru_tc<<<96, 128>>>(rnn, out_h);
    k_attn<<<Nq / 32 / 8, 256>>>(obs, Win, bin, Wout, bout);
    cudaFuncSetAttribute(k_mlp_h, cudaFuncAttributeMaxDynamicSharedMemorySize, SM_TOT);
    k_mlp_h<<<Nq / 64, 256, SM_TOT>>>(b0, b1, oW, ob, out_val);
}

// round 12
// speedup vs baseline: 1.0272x; 1.0272x over previous
#include <cuda_runtime.h>
#include <cuda_bf16.h>
#include <cstdint>

#define Bq 2048
#define Tq 128
#define Nq (Bq*Tq)

// ---------------- scratch (no allocations allowed) ----------------
__device__ float g_air[(size_t)Nq * 32];
__device__ float g_m1 [(size_t)Nq * 32];
__device__ float g_m2 [(size_t)Nq * 32];
__device__ float g_fusion[(size_t)Nq * 64];
// prepacked bf16 hi/lo MLP weights, row-major [n][k]
__device__ __nv_bfloat16 g_W0h[256 * 64];
__device__ __nv_bfloat16 g_W0l[256 * 64];
__device__ __nv_bfloat16 g_W1h[256 * 256];
__device__ __nv_bfloat16 g_W1l[256 * 256];
// GRU tensor-core prepack: B-fragments, biases, X A-fragments
__device__ uint2  g_gB[2 * 36 * 2 * 32];            // [ty][pair][part][lane] -> 2 regs
__device__ float  g_gBias[2 * 128];
__device__ uint4  g_gX[(size_t)384 * 128 * 32 * 2]; // [(group*128+t)*32+lane]*2+part

__device__ __forceinline__ float tanhap(float x) {
    float y;
    asm("tanh.approx.f32 %0, %1;" : "=f"(y) : "f"(x));
    return y;
}
__device__ __forceinline__ float fsig(float x) {           // sigmoid via tanh
    return fmaf(0.5f, tanhap(0.5f * x), 0.5f);
}

// packed 2xfp32 FMA
union F2U { float2 f; unsigned long long u; };
__device__ __forceinline__ float2 ffma2(float2 a, float2 b, float2 c) {
    F2U A, B, C, D;
    A.f = a; B.f = b; C.f = c;
    asm("fma.rn.f32x2 %0, %1, %2, %3;" : "=l"(D.u) : "l"(A.u), "l"(B.u), "l"(C.u));
    return D.f;
}
__device__ __forceinline__ float2 dot4_2(float4 a, float4 b, float2 acc) {
    acc = ffma2(make_float2(a.x, a.y), make_float2(b.x, b.y), acc);
    acc = ffma2(make_float2(a.z, a.w), make_float2(b.z, b.w), acc);
    return acc;
}

// ---------------- mma.sync / cp.async helpers ----------------
__device__ __forceinline__ uint32_t smem_u32(const void* p) {
    uint32_t a;
    asm("{ .reg .u64 t; cvta.to.shared.u64 t, %1; cvt.u32.u64 %0, t; }" : "=r"(a) : "l"(p));
    return a;
}
__device__ __forceinline__ void ldsm4(uint32_t* a, uint32_t addr) {
    asm volatile("ldmatrix.sync.aligned.m8n8.x4.shared.b16 {%0,%1,%2,%3}, [%4];"
        : "=r"(a[0]), "=r"(a[1]), "=r"(a[2]), "=r"(a[3]) : "r"(addr));
}
__device__ __forceinline__ void ldsm2(uint32_t* b, uint32_t addr) {
    asm volatile("ldmatrix.sync.aligned.m8n8.x2.shared.b16 {%0,%1}, [%2];"
        : "=r"(b[0]), "=r"(b[1]) : "r"(addr));
}
__device__ __forceinline__ void mma16816(float* c, const uint32_t* a, const uint32_t* b) {
    asm volatile("mma.sync.aligned.m16n8k16.row.col.f32.bf16.bf16.f32 "
        "{%0,%1,%2,%3}, {%4,%5,%6,%7}, {%8,%9}, {%0,%1,%2,%3};"
        : "+f"(c[0]), "+f"(c[1]), "+f"(c[2]), "+f"(c[3])
        : "r"(a[0]), "r"(a[1]), "r"(a[2]), "r"(a[3]), "r"(b[0]), "r"(b[1]));
}
// first-MMA form: C-out gets A*B + bias (separate C-in, no init MOVs)
__device__ __forceinline__ void mma16816_init(float* c, float c0, float c1,
                                              const uint32_t* a, const uint32_t* b) {
    asm volatile("mma.sync.aligned.m16n8k16.row.col.f32.bf16.bf16.f32 "
        "{%0,%1,%2,%3}, {%4,%5,%6,%7}, {%8,%9}, {%10,%11,%10,%11};"
        : "=f"(c[0]), "=f"(c[1]), "=f"(c[2]), "=f"(c[3])
        : "r"(a[0]), "r"(a[1]), "r"(a[2]), "r"(a[3]), "r"(b[0]), "r"(b[1]),
          "f"(c0), "f"(c1));
}
__device__ __forceinline__ void cpa16(uint32_t dst, const void* src) {
    asm volatile("cp.async.cg.shared.global [%0], [%1], 16;" :: "r"(dst), "l"(src));
}
#define CPA_COMMIT() asm volatile("cp.async.commit_group;" ::: "memory")
#define SWZ(x) ((x) ^ (((x) >> 3) & 0x70))

__device__ __forceinline__ __nv_bfloat162 split_hi(float a, float b) {
    __nv_bfloat162 h; h.x = __float2bfloat16(a); h.y = __float2bfloat16(b); return h;
}
__device__ __forceinline__ __nv_bfloat162 split_lo(float a, float b, __nv_bfloat162 h) {
    __nv_bfloat162 l;
    l.x = __float2bfloat16(a - __bfloat162float(h.x));
    l.y = __float2bfloat16(b - __bfloat162float(h.y));
    return l;
}
__device__ __forceinline__ uint32_t bf2u(__nv_bfloat162 v) {
    return *reinterpret_cast<uint32_t*>(&v);
}
// packed split: one bf16x2 cvt for hi, shift-reconstruct, one cvt for lo
__device__ __forceinline__ void split2(float a, float b, uint32_t& hi, uint32_t& lo) {
    uint32_t h;
    asm("cvt.rn.bf16x2.f32 %0, %1, %2;" : "=r"(h) : "f"(b), "f"(a)); // lo16=a, hi16=b
    float f0 = __uint_as_float(h << 16);
    float f1 = __uint_as_float(h & 0xffff0000u);
    float l0 = a - f0, l1 = b - f1;
    uint32_t l;
    asm("cvt.rn.bf16x2.f32 %0, %1, %2;" : "=r"(l) : "f"(l1), "f"(l0));
    hi = h; lo = l;
}

// GRU tile-pair tables, kt-OUTER ordering so consecutive MMAs hit different
// accumulators. nt 0-7: r,z; nt 8-11: hn (h only); nt 12-15: xn (x only).
#define GRU_PNT {0,1,2,3,4,5,6,7,8,9,10,11, 0,1,2,3,4,5,6,7,8,9,10,11, 0,1,2,3,4,5,6,7,12,13,14,15}
#define GRU_PKT {0,0,0,0,0,0,0,0,0,0,0,0,  1,1,1,1,1,1,1,1,1,1,1,1,   2,2,2,2,2,2,2,2,2,2,2,2}

// ================= MLP weight prepack =================
__global__ void k_pack(const float* __restrict__ W0, const float* __restrict__ W1) {
    int i = blockIdx.x * 256 + threadIdx.x;
    if (i < 16384) {
        float w = W0[i];
        __nv_bfloat16 h = __float2bfloat16(w);
        g_W0h[i] = h;
        g_W0l[i] = __float2bfloat16(w - __bfloat162float(h));
    } else if (i < 16384 + 65536) {
        int j = i - 16384;
        float w = W1[j];
        __nv_bfloat16 h = __float2bfloat16(w);
        g_W1h[j] = h;
        g_W1l[j] = __float2bfloat16(w - __bfloat162float(h));
    }
}

// ================= GRU weight/bias prepack =================
__device__ __forceinline__ float gru_bval(
    int k, int n, const float* Whh, const float* Wih, const float* encW, int KIN)
{
    int blk = n >> 5, j = n & 31;
    if (k < 32) {
        if (blk == 3) return 0.f;
        return Whh[(blk * 32 + j) * 32 + k];
    }
    int f = k - 32;
    if (f >= KIN || blk == 2) return 0.f;
    int row = (blk == 3) ? 64 + j : blk * 32 + j;
    float s = 0.f;
    #pragma unroll
    for (int m = 0; m < 32; m++) s = fmaf(Wih[row * 32 + m], encW[m * KIN + f], s);
    return s;
}

__global__ void k_packg_w(
    const float* __restrict__ aWih, const float* __restrict__ aWhh,
    const float* __restrict__ abih, const float* __restrict__ abhh,
    const float* __restrict__ eAW,  const float* __restrict__ eAb,
    const float* __restrict__ mWih, const float* __restrict__ mWhh,
    const float* __restrict__ mbih, const float* __restrict__ mbhh,
    const float* __restrict__ eMW,  const float* __restrict__ eMb)
{
    const int PNT[36] = GRU_PNT;
    const int PKT[36] = GRU_PKT;
    int tid = blockIdx.x * 256 + threadIdx.x;
    if (tid < 2304) {
        int lane = tid & 31;
        int p = (tid >> 5) % 36;
        int ty = tid / (36 * 32);
        const float* Whh = ty ? mWhh : aWhh;
        const float* Wih = ty ? mWih : aWih;
        const float* eW  = ty ? eMW  : eAW;
        int KIN = ty ? 4 : 7;
        int g = lane >> 2, tq = lane & 3;
        int n = PNT[p] * 8 + g;
        uint32_t rh[2], rl[2];
        #pragma unroll
        for (int r = 0; r < 2; r++) {
            int k0 = PKT[p] * 16 + tq * 2 + r * 8;
            float v0 = gru_bval(k0,     n, Whh, Wih, eW, KIN);
            float v1 = gru_bval(k0 + 1, n, Whh, Wih, eW, KIN);
            __nv_bfloat162 hh = split_hi(v0, v1);
            __nv_bfloat162 ll = split_lo(v0, v1, hh);
            rh[r] = bf2u(hh); rl[r] = bf2u(ll);
        }
        int base = (ty * 72 + p * 2) * 32 + lane;
        g_gB[base]      = make_uint2(rh[0], rh[1]);
        g_gB[base + 32] = make_uint2(rl[0], rl[1]);
    } else if (tid < 2304 + 256) {
        int u = tid - 2304;
        int ty = u >> 7, n = u & 127;
        const float* Wih = ty ? mWih : aWih;
        const float* bih = ty ? mbih : abih;
        const float* bhh = ty ? mbhh : abhh;
        const float* eB  = ty ? eMb  : eAb;
        int blk = n >> 5, j = n & 31;
        float b;
        if (blk == 2) {
            b = bhh[64 + j];
        } else {
            int row = (blk == 3) ? 64 + j : blk * 32 + j;
            float bc = bih[row];
            #pragma unroll
            for (int m = 0; m < 32; m++) bc = fmaf(Wih[row * 32 + m], eB[m], bc);
            b = (blk < 2) ? bc + bhh[row] : bc;
        }
        g_gBias[ty * 128 + n] = b;
    }
}

// X A-fragment prepack: per (group, t, lane) 4 hi + 4 lo regs.
__global__ void k_packg_x(const float* __restrict__ obs) {
    int tid = blockIdx.x * 256 + threadIdx.x;
    int lane = tid & 31;
    int s = tid >> 5;
    int t = s & 127;
    int gr = s >> 7;
    int g = lane >> 2, tq = lane & 3;

    int KIN, xoff;
    int b0;
    if (gr < 128) { KIN = 7; xoff = 8; b0 = gr * 16; }
    else {
        int gi = gr - 128;
        KIN = 4;
        xoff = (gi < 128) ? 0 : 4;
        b0 = (gi < 128) ? gi * 16 : (gi - 128) * 16;
    }
    uint32_t hr[4], lr[4];
    #pragma unroll
    for (int r = 0; r < 4; r++) {
        int row = g + 8 * (r & 1);
        int k0 = tq * 2 + (r >> 1) * 8;
        float v0 = 0.f, v1 = 0.f;
        if (k0 < KIN)
            v0 = obs[(size_t)(b0 + row) * Tq * 15 + t * 15 + xoff + k0];
        if (k0 + 1 < KIN)
            v1 = obs[(size_t)(b0 + row) * Tq * 15 + t * 15 + xoff + k0 + 1];
        __nv_bfloat162 hh = split_hi(v0, v1);
        __nv_bfloat162 ll = split_lo(v0, v1, hh);
        hr[r] = bf2u(hh); lr[r] = bf2u(ll);
    }
    size_t idx = ((size_t)(gr * 128 + t) * 32 + lane) * 2;
    g_gX[idx]     = make_uint4(hr[0], hr[1], hr[2], hr[3]);
    g_gX[idx + 1] = make_uint4(lr[0], lr[1], lr[2], lr[3]);
}

// ====== GRU: tensor-core recurrence, 1 warp/CTA (384 CTAs -> 148 SMs) ======
__global__ void __launch_bounds__(32) k_gru_tc(
    const float* __restrict__ rnn, float* __restrict__ next_h)
{
    const int PNT[36] = GRU_PNT;
    const int PKT[36] = GRU_PKT;
    int lane = threadIdx.x & 31;
    int w = blockIdx.x;                          // 0..383
    int g = lane >> 2, tq = lane & 3;

    int ty; float* featb; int ib; bool is_air = (w < 128);
    if (is_air) { ty = 0; featb = g_air; ib = w * 16; }
    else {
        ty = 1;
        int gi = w - 128;
        if (gi < 128) { featb = g_m1; ib = gi * 16; }
        else          { featb = g_m2; ib = (gi - 128) * 16; }
    }
    int gi = w - 128;

    float hv[4][4];
    #pragma unroll
    for (int nt = 0; nt < 4; nt++) {
        int col = nt * 8 + 2 * tq;
        #pragma unroll
        for (int rh = 0; rh < 2; rh++) {
            int row = g + 8 * rh;
            const float* src;
            if (is_air) src = rnn + (size_t)(w * 16 + row) * 96 + col;
            else {
                int i = gi * 16 + row;
                src = rnn + (size_t)(i >> 1) * 96 + 32 + 32 * (i & 1) + col;
            }
            float2 v = *(const float2*)src;
            hv[nt][rh * 2]     = v.x;
            hv[nt][rh * 2 + 1] = v.y;
        }
    }
    float bias[16][2];
    #pragma unroll
    for (int nt = 0; nt < 16; nt++) {
        float2 v = *(const float2*)(g_gBias + ty * 128 + nt * 8 + 2 * tq);
        bias[nt][0] = v.x; bias[nt][1] = v.y;
    }
    uint32_t Ah[2][4], Al[2][4];
    #pragma unroll
    for (int nt = 0; nt < 4; nt++) {
        int kt = nt >> 1;
        int o = (nt & 1) ? 2 : 0;
        split2(hv[nt][0], hv[nt][1], Ah[kt][o],     Al[kt][o]);
        split2(hv[nt][2], hv[nt][3], Ah[kt][o + 1], Al[kt][o + 1]);
    }

    const uint2* gBb = g_gB + ty * 72 * 32 + lane;
    const uint4* gXb = g_gX + ((size_t)w * 128) * 32 * 2 + lane * 2;
    float* fr0 = featb + (size_t)(ib + g)     * Tq * 32 + 2 * tq;
    float* fr1 = featb + (size_t)(ib + g + 8) * Tq * 32 + 2 * tq;

    uint4 xh_cur = gXb[0], xl_cur = gXb[1];

    #pragma unroll 1
    for (int t = 0; t < Tq; t++) {
        int tn = (t + 1 < Tq) ? t + 1 : t;
        uint4 xh_nxt = gXb[(size_t)tn * 64];
        uint4 xl_nxt = gXb[(size_t)tn * 64 + 1];

        uint32_t Xh[4] = {xh_cur.x, xh_cur.y, xh_cur.z, xh_cur.w};
        uint32_t Xl[4] = {xl_cur.x, xl_cur.y, xl_cur.z, xl_cur.w};
        float C[16][4];
        // first MMA of each tile carries bias as C-in (no init MOVs)
        #pragma unroll
        for (int p = 0; p < 36; p++) {
            int nt = PNT[p], kt = PKT[p];
            uint2 bh = gBb[(p * 2) * 32];
            uint2 bl = gBb[(p * 2 + 1) * 32];
            const uint32_t* ah = (kt == 2) ? Xh : Ah[kt];
            const uint32_t* al = (kt == 2) ? Xl : Al[kt];
            if (p < 12 || p >= 32)
                mma16816_init(C[nt], bias[nt][0], bias[nt][1], ah, (const uint32_t*)&bh);
            else
                mma16816(C[nt], ah, (const uint32_t*)&bh);
            mma16816(C[nt], ah, (const uint32_t*)&bl);
            mma16816(C[nt], al, (const uint32_t*)&bh);
        }
        #pragma unroll
        for (int nt = 0; nt < 4; nt++) {
            #pragma unroll
            for (int j = 0; j < 4; j++) {
                float r = fsig(C[nt][j]);
                float z = fsig(C[nt + 4][j]);
                float n = tanhap(fmaf(r, C[nt + 8][j], C[nt + 12][j]));
                hv[nt][j] = n + z * (hv[nt][j] - n);
            }
            *(float2*)(fr0 + (size_t)t * 32 + nt * 8) = make_float2(hv[nt][0], hv[nt][1]);
            *(float2*)(fr1 + (size_t)t * 32 + nt * 8) = make_float2(hv[nt][2], hv[nt][3]);
            int kt = nt >> 1;
            int o = (nt & 1) ? 2 : 0;
            split2(hv[nt][0], hv[nt][1], Ah[kt][o],     Al[kt][o]);
            split2(hv[nt][2], hv[nt][3], Ah[kt][o + 1], Al[kt][o + 1]);
        }
        xh_cur = xh_nxt; xl_cur = xl_nxt;
    }
    #pragma unroll
    for (int nt = 0; nt < 4; nt++) {
        int col = nt * 8 + 2 * tq;
        #pragma unroll
        for (int rh = 0; rh < 2; rh++) {
            int row = g + 8 * rh;
            float2 v = make_float2(hv[nt][rh * 2], hv[nt][rh * 2 + 1]);
            float* dst;
            if (is_air) dst = next_h + (size_t)(w * 16 + row) * 96 + col;
            else {
                int i = gi * 16 + row;
                dst = next_h + (size_t)(i >> 1) * 96 + 32 + 32 * (i & 1) + col;
            }
            *(float2*)dst = v;
        }
    }
}

// ================= attention + fusion (unchanged) =================
__global__ void __launch_bounds__(256) k_attn(
    const float* __restrict__ obs,
    const float* __restrict__ Win, const float* __restrict__ bin,
    const float* __restrict__ Wout, const float* __restrict__ bout)
{
    __shared__ float Ws[96 * 32];
    __shared__ float Wo[32 * 32];
    __shared__ float bs[96], bo[32];
    int t = threadIdx.x;
    for (int i = t; i < 96 * 32; i += 256) Ws[i] = Win[i];
    for (int i = t; i < 32 * 32; i += 256) Wo[i] = Wout[i];
    if (t < 96) bs[t] = bin[t];
    if (t < 32) bo[t] = bout[t];
    __syncthreads();

    int warp = blockIdx.x * 8 + (t >> 5);
    int la = t & 31;
    int n = warp * 32 + la;

    float4 A[8], M1[8], M2[8];
    const float4* ap = (const float4*)(g_air + (size_t)n * 32);
    const float4* p1 = (const float4*)(g_m1 + (size_t)n * 32);
    const float4* p2 = (const float4*)(g_m2 + (size_t)n * 32);
    #pragma unroll
    for (int i = 0; i < 8; i++) { A[i] = ap[i]; M1[i] = p1[i]; M2[i] = p2[i]; }

    const float* op = obs + (size_t)n * 15;
    float o0=op[0],o1=op[1],o2=op[2],o3=op[3],o4=op[4],o5=op[5],o6=op[6],o7=op[7];
    const float T1 = 1.001e-5f, T0 = 1e-8f;
    bool mk0 = (fabsf(o0-1.f)<=T1) && (fabsf(o1)<=T0) && (fabsf(o2-1.f)<=T1) && (fabsf(o3)<=T0);
    bool mk1 = (fabsf(o4-1.f)<=T1) && (fabsf(o5)<=T0) && (fabsf(o6-1.f)<=T1) && (fabsf(o7)<=T0);

    float q[32];
    #pragma unroll
    for (int c = 0; c < 32; c++) {
        float2 a = make_float2(bs[c], 0.f);
        const float4* w = (const float4*)(Ws + c * 32);
        #pragma unroll
        for (int k = 0; k < 8; k++) a = dot4_2(A[k], w[k], a);
        q[c] = a.x + a.y;
    }
    float s1[2] = {0.f, 0.f}, s2[2] = {0.f, 0.f};
    #pragma unroll
    for (int c = 0; c < 32; c++) {
        const float4* w = (const float4*)(Ws + (32 + c) * 32);
        float2 k1 = make_float2(bs[32 + c], 0.f), k2 = make_float2(0.f, 0.f);
        #pragma unroll
        for (int k = 0; k < 8; k++) { k1 = dot4_2(M1[k], w[k], k1); k2 = dot4_2(M2[k], w[k], k2); }
        int hh = c >> 4;
        s1[hh] = fmaf(q[c], k1.x + k1.y, s1[hh]);
        s2[hh] = fmaf(q[c], k2.x + k2.y + bs[32 + c], s2[hh]);
    }
    float w1[2], w2[2];
    #pragma unroll
    for (int hh = 0; hh < 2; hh++) {
        float a = s1[hh] * 0.25f + (mk0 ? -1e9f : 0.f);
        float b = s2[hh] * 0.25f + (mk1 ? -1e9f : 0.f);
        float m = fmaxf(a, b);
        float e1 = __expf(a - m), e2 = __expf(b - m);
        float inv = __fdividef(1.0f, e1 + e2);
        w1[hh] = e1 * inv; w2[hh] = e2 * inv;
    }
    float ctx[32];
    #pragma unroll
    for (int c = 0; c < 32; c++) {
        const float4* w = (const float4*)(Ws + (64 + c) * 32);
        float2 v1 = make_float2(bs[64 + c], 0.f), v2 = make_float2(0.f, 0.f);
        #pragma unroll
        for (int k = 0; k < 8; k++) { v1 = dot4_2(M1[k], w[k], v1); v2 = dot4_2(M2[k], w[k], v2); }
        int hh = c >> 4;
        ctx[c] = w1[hh] * (v1.x + v1.y) + w2[hh] * (v2.x + v2.y + bs[64 + c]);
    }
    bool allm = mk0 && mk1;
    float at[32];
    #pragma unroll
    for (int o = 0; o < 32; o++) {
        float2 a = make_float2(bo[o], 0.f);
        const float4* w = (const float4*)(Wo + o * 32);
        #pragma unroll
        for (int c4 = 0; c4 < 8; c4++) {
            float4 cv = make_float4(ctx[4*c4], ctx[4*c4+1], ctx[4*c4+2], ctx[4*c4+3]);
            a = dot4_2(cv, w[c4], a);
        }
        at[o] = allm ? 0.0f : (a.x + a.y);
    }
    float4* fr = (float4*)(g_fusion + (size_t)n * 64);
    #pragma unroll
    for (int i = 0; i < 8; i++) fr[i] = A[i];
    #pragma unroll
    for (int i = 0; i < 8; i++)
        fr[8 + i] = make_float4(at[4*i], at[4*i+1], at[4*i+2], at[4*i+3]);
}

// ======= HMMA MLP: M=64/CTA, 2 CTAs/SM (unchanged) =======
#define SM_B0  0
#define SM_B1  1024
#define SM_OW  2048
#define SM_A1H 3072
#define SM_A1L 36864
#define SM_WB  70656
#define SM_RED 70656
#define SM_TOT 111616
#define SM_A0H 3072
#define SM_A0L 11264
#define SM_W0H 19456
#define SM_W0L 52224
#define PA1 528
#define PW1 80

__global__ void __launch_bounds__(256, 2) k_mlp_h(
    const float* __restrict__ b0, const float* __restrict__ b1,
    const float* __restrict__ oW, const float* __restrict__ ob,
    float* __restrict__ val)
{
    extern __shared__ char smem[];
    uint32_t smb = smem_u32(smem);
    int tid = threadIdx.x, wid = tid >> 5, lane = tid & 31;
    int g = lane >> 2, tq = lane & 3;
    int row0 = blockIdx.x * 64;
    int n0w = wid * 32;

    float* b0s = (float*)(smem + SM_B0);
    float* b1s = (float*)(smem + SM_B1);
    float* ows = (float*)(smem + SM_OW);
    b0s[tid] = b0[tid]; b1s[tid] = b1[tid]; ows[tid] = oW[tid];

    int aro = lane & 15;
    int aco = (lane >> 1) & 8;
    int bro = lane & 7;
    int bco = lane & 8;

    #pragma unroll
    for (int q = 0; q < 16; q++) {
        int id = tid + 256 * q;
        int part = id >> 11;
        int u = id & 2047;
        int nn = u >> 3, j = u & 7;
        uint32_t dst = smb + (part ? SM_W0L : SM_W0H) + SWZ((uint32_t)(nn * 128 + j * 16));
        const __nv_bfloat16* src = (part ? g_W0l : g_W0h) + nn * 64 + j * 8;
        cpa16(dst, src);
    }
    CPA_COMMIT();
    {
        const float4* Fg = (const float4*)g_fusion + (size_t)row0 * 16;
        #pragma unroll
        for (int q = 0; q < 4; q++) {
            int id = tid + 256 * q;
            int r = id >> 4, c4 = id & 15;
            float4 v = Fg[id];
            __nv_bfloat162 h0 = split_hi(v.x, v.y), l0 = split_lo(v.x, v.y, h0);
            __nv_bfloat162 h1 = split_hi(v.z, v.w), l1 = split_lo(v.z, v.w, h1);
            uint32_t o0 = SWZ((uint32_t)(r * 128 + c4 * 8));
            uint32_t o1 = SWZ((uint32_t)(r * 128 + c4 * 8 + 4));
            *(__nv_bfloat162*)(smem + SM_A0H + o0) = h0;
            *(__nv_bfloat162*)(smem + SM_A0H + o1) = h1;
            *(__nv_bfloat162*)(smem + SM_A0L + o0) = l0;
            *(__nv_bfloat162*)(smem + SM_A0L + o1) = l1;
        }
    }
    asm volatile("cp.async.wait_group 0;" ::: "memory");
    __syncthreads();

    float acc[4][4][4];
    #pragma unroll
    for (int m = 0; m < 4; m++)
        #pragma unroll
        for (int nt = 0; nt < 4; nt++)
            #pragma unroll
            for (int r = 0; r < 4; r++) acc[m][nt][r] = 0.f;
    #pragma unroll 1
    for (int k16 = 0; k16 < 4; k16++) {
        int kc = k16 * 16;
        uint32_t bh[4][2], bl[4][2];
        #pragma unroll
        for (int nt = 0; nt < 4; nt++) {
            uint32_t ba = SWZ((uint32_t)((n0w + 8 * nt + bro) * 128 + (kc + bco) * 2));
            ldsm2(bh[nt], smb + SM_W0H + ba);
            ldsm2(bl[nt], smb + SM_W0L + ba);
        }
        #pragma unroll
        for (int m = 0; m < 4; m++) {
            uint32_t ah[4], al[4];
            uint32_t aa = SWZ((uint32_t)((m * 16 + aro) * 128 + (kc + aco) * 2));
            ldsm4(ah, smb + SM_A0H + aa);
            ldsm4(al, smb + SM_A0L + aa);
            #pragma unroll
            for (int nt = 0; nt < 4; nt++) {
                mma16816(acc[m][nt], ah, bh[nt]);
                mma16816(acc[m][nt], ah, bl[nt]);
                mma16816(acc[m][nt], al, bh[nt]);
            }
        }
    }
    __syncthreads();

    #pragma unroll
    for (int q = 0; q < 8; q++) {
        int id = tid + 256 * q;
        int part = id >> 10;
        int u = id & 1023;
        int r = u >> 2, j = u & 3;
        const __nv_bfloat16* src = (part ? g_W1l : g_W1h) + r * 256 + j * 8;
        cpa16(smb + SM_WB + part * 20480 + r * PW1 + j * 16, src);
    }
    CPA_COMMIT();

    #pragma unroll
    for (int m = 0; m < 4; m++)
        #pragma unroll
        for (int nt = 0; nt < 4; nt++) {
            int c0 = n0w + 8 * nt + 2 * tq;
            float v0 = acc[m][nt][0] + b0s[c0];
            float v1 = acc[m][nt][1] + b0s[c0 + 1];
            float v2 = acc[m][nt][2] + b0s[c0];
            float v3 = acc[m][nt][3] + b0s[c0 + 1];
            v0 = v0 > 0.f ? v0 : 0.01f * v0;
            v1 = v1 > 0.f ? v1 : 0.01f * v1;
            v2 = v2 > 0.f ? v2 : 0.01f * v2;
            v3 = v3 > 0.f ? v3 : 0.01f * v3;
            int r0 = 16 * m + g, r1 = r0 + 8;
            __nv_bfloat162 h01 = split_hi(v0, v1), l01 = split_lo(v0, v1, h01);
            __nv_bfloat162 h23 = split_hi(v2, v3), l23 = split_lo(v2, v3, h23);
            *(__nv_bfloat162*)(smem + SM_A1H + r0 * PA1 + c0 * 2) = h01;
            *(__nv_bfloat162*)(smem + SM_A1L + r0 * PA1 + c0 * 2) = l01;
            *(__nv_bfloat162*)(smem + SM_A1H + r1 * PA1 + c0 * 2) = h23;
            *(__nv_bfloat162*)(smem + SM_A1L + r1 * PA1 + c0 * 2) = l23;
        }

    float a2[4][4][4];
    #pragma unroll
    for (int m = 0; m < 4; m++)
        #pragma unroll
        for (int nt = 0; nt < 4; nt++)
            #pragma unroll
            for (int r = 0; r < 4; r++) a2[m][nt][r] = 0.f;
    #pragma unroll 1
    for (int c = 0; c < 8; c++) {
        asm volatile("cp.async.wait_group 0;" ::: "memory");
        __syncthreads();
        uint32_t wb = smb + SM_WB;
        uint32_t bh0[4][2], bl0[4][2], bh1[4][2], bl1[4][2];
        #pragma unroll
        for (int nt = 0; nt < 4; nt++) {
            uint32_t ba0 = (uint32_t)((n0w + 8 * nt + bro) * PW1 + (bco) * 2);
            uint32_t ba1 = ba0 + 32;
            ldsm2(bh0[nt], wb + ba0);
            ldsm2(bl0[nt], wb + 20480 + ba0);
            ldsm2(bh1[nt], wb + ba1);
            ldsm2(bl1[nt], wb + 20480 + ba1);
        }
        __syncthreads();
        if (c + 1 < 8) {
            #pragma unroll
            for (int q = 0; q < 8; q++) {
                int id = tid + 256 * q;
                int part = id >> 10;
                int u = id & 1023;
                int r = u >> 2, j = u & 3;
                const __nv_bfloat16* src = (part ? g_W1l : g_W1h) + r * 256 + (c + 1) * 32 + j * 8;
                cpa16(smb + SM_WB + part * 20480 + r * PW1 + j * 16, src);
            }
            CPA_COMMIT();
        }
        #pragma unroll
        for (int m = 0; m < 4; m++) {
            uint32_t ah[4], al[4];
            uint32_t aa = (uint32_t)((m * 16 + aro) * PA1 + (c * 32 + aco) * 2);
            ldsm4(ah, smb + SM_A1H + aa);
            ldsm4(al, smb + SM_A1L + aa);
            #pragma unroll
            for (int nt = 0; nt < 4; nt++) {
                mma16816(a2[m][nt], ah, bh0[nt]);
                mma16816(a2[m][nt], ah, bl0[nt]);
                mma16816(a2[m][nt], al, bh0[nt]);
            }
            uint32_t aa1 = aa + 32;
            ldsm4(ah, smb + SM_A1H + aa1);
            ldsm4(al, smb + SM_A1L + aa1);
            #pragma unroll
            for (int nt = 0; nt < 4; nt++) {
                mma16816(a2[m][nt], ah, bh1[nt]);
                mma16816(a2[m][nt], ah, bl1[nt]);
                mma16816(a2[m][nt], al, bh1[nt]);
            }
        }
    }

    float* red = (float*)(smem + SM_RED);
    float p[4][2];
    #pragma unroll
    for (int m = 0; m < 4; m++) { p[m][0] = 0.f; p[m][1] = 0.f; }
    #pragma unroll
    for (int m = 0; m < 4; m++)
        #pragma unroll
        for (int nt = 0; nt < 4; nt++) {
            int c0 = n0w + 8 * nt + 2 * tq;
            float w0v = ows[c0], w1v = ows[c0 + 1];
            float bb0 = b1s[c0], bb1 = b1s[c0 + 1];
            float v0 = a2[m][nt][0] + bb0;
            float v1 = a2[m][nt][1] + bb1;
            float v2 = a2[m][nt][2] + bb0;
            float v3 = a2[m][nt][3] + bb1;
            v0 = v0 > 0.f ? v0 : 0.01f * v0;
            v1 = v1 > 0.f ? v1 : 0.01f * v1;
            v2 = v2 > 0.f ? v2 : 0.01f * v2;
            v3 = v3 > 0.f ? v3 : 0.01f * v3;
            p[m][0] = fmaf(v0, w0v, p[m][0]);
            p[m][0] = fmaf(v1, w1v, p[m][0]);
            p[m][1] = fmaf(v2, w0v, p[m][1]);
            p[m][1] = fmaf(v3, w1v, p[m][1]);
        }
    #pragma unroll
    for (int off = 1; off <= 2; off <<= 1)
        #pragma unroll
        for (int m = 0; m < 4; m++) {
            p[m][0] += __shfl_xor_sync(0xffffffffu, p[m][0], off);
            p[m][1] += __shfl_xor_sync(0xffffffffu, p[m][1], off);
        }
    if (tq == 0) {
        #pragma unroll
        for (int m = 0; m < 4; m++) {
            red[wid * 64 + 16 * m + g]     = p[m][0];
            red[wid * 64 + 16 * m + g + 8] = p[m][1];
        }
    }
    __syncthreads();
    if (tid < 64) {
        float s = __ldg(ob);
        #pragma unroll
        for (int w8 = 0; w8 < 8; w8++) s += red[w8 * 64 + tid];
        val[row0 + tid] = s;
    }
}

extern "C" void kernel_launch(void* const* d_in, const int* in_sizes, int n_in,
                              void* d_out, int out_size) {
    const float* obs   = (const float*)d_in[0];
    const float* rnn   = (const float*)d_in[1];
    const float* eAW   = (const float*)d_in[2];
    const float* eAb   = (const float*)d_in[3];
    const float* eMW   = (const float*)d_in[4];
    const float* eMb   = (const float*)d_in[5];
    const float* aWih  = (const float*)d_in[6];
    const float* aWhh  = (const float*)d_in[7];
    const float* abih  = (const float*)d_in[8];
    const float* abhh  = (const float*)d_in[9];
    const float* mWih  = (const float*)d_in[10];
    const float* mWhh  = (const float*)d_in[11];
    const float* mbih  = (const float*)d_in[12];
    const float* mbhh  = (const float*)d_in[13];
    const float* Win   = (const float*)d_in[14];
    const float* bin   = (const float*)d_in[15];
    const float* Wout  = (const float*)d_in[16];
    const float* bout  = (const float*)d_in[17];
    const float* W0    = (const float*)d_in[18];
    const float* b0    = (const float*)d_in[19];
    const float* W1    = (const float*)d_in[20];
    const float* b1    = (const float*)d_in[21];
    const float* oW    = (const float*)d_in[22];
    const float* ob    = (const float*)d_in[23];

    float* out_val = (float*)d_out;
    float* out_h   = (float*)d_out + Nq;

    k_pack<<<320, 256>>>(W0, W1);
    k_packg_w<<<10, 256>>>(aWih, aWhh, abih, abhh, eAW, eAb,
                           mWih, mWhh, mbih, mbhh, eMW, eMb);
    k_packg_x<<<6144, 256>>>(obs);
    k_gru_tc<<<384, 32>>>(rnn, out_h);
    k_attn<<<Nq / 32 / 8, 256>>>(obs, Win, bin, Wout, bout);
    cudaFuncSetAttribute(k_mlp_h, cudaFuncAttributeMaxDynamicSharedMemorySize, SM_TOT);
    k_mlp_h<<<Nq / 64, 256, SM_TOT>>>(b0, b1, oW, ob, out_val);
}

// round 13
// speedup vs baseline: 1.1737x; 1.1427x over previous
#include <cuda_runtime.h>
#include <cuda_bf16.h>
#include <cstdint>

#define Bq 2048
#define Tq 128
#define Nq (Bq*Tq)

// ---------------- scratch (no allocations allowed) ----------------
__device__ float g_air[(size_t)Nq * 32];
__device__ float g_m1 [(size_t)Nq * 32];
__device__ float g_m2 [(size_t)Nq * 32];
__device__ float g_fusion[(size_t)Nq * 64];
// MLP weights prepacked in mma B-fragment layout (hi/lo split-bf16)
__device__ uint2 g_W0f[8192];    // [k16(4)][ntg(32)][part(2)][lane(32)]
__device__ uint2 g_W1f[32768];   // [ck(16)][ntg(32)][part(2)][lane(32)]
// GRU tensor-core prepack: B-fragments, biases, X A-fragments
__device__ uint2  g_gB[2 * 36 * 2 * 32];
__device__ float  g_gBias[2 * 128];
__device__ uint4  g_gX[(size_t)384 * 128 * 32 * 2];

__device__ __forceinline__ float tanhap(float x) {
    float y;
    asm("tanh.approx.f32 %0, %1;" : "=f"(y) : "f"(x));
    return y;
}
__device__ __forceinline__ float fsig(float x) {
    return fmaf(0.5f, tanhap(0.5f * x), 0.5f);
}

union F2U { float2 f; unsigned long long u; };
__device__ __forceinline__ float2 ffma2(float2 a, float2 b, float2 c) {
    F2U A, B, C, D;
    A.f = a; B.f = b; C.f = c;
    asm("fma.rn.f32x2 %0, %1, %2, %3;" : "=l"(D.u) : "l"(A.u), "l"(B.u), "l"(C.u));
    return D.f;
}
__device__ __forceinline__ float2 dot4_2(float4 a, float4 b, float2 acc) {
    acc = ffma2(make_float2(a.x, a.y), make_float2(b.x, b.y), acc);
    acc = ffma2(make_float2(a.z, a.w), make_float2(b.z, b.w), acc);
    return acc;
}

__device__ __forceinline__ uint32_t smem_u32(const void* p) {
    uint32_t a;
    asm("{ .reg .u64 t; cvta.to.shared.u64 t, %1; cvt.u32.u64 %0, t; }" : "=r"(a) : "l"(p));
    return a;
}
__device__ __forceinline__ void ldsm4(uint32_t* a, uint32_t addr) {
    asm volatile("ldmatrix.sync.aligned.m8n8.x4.shared.b16 {%0,%1,%2,%3}, [%4];"
        : "=r"(a[0]), "=r"(a[1]), "=r"(a[2]), "=r"(a[3]) : "r"(addr));
}
__device__ __forceinline__ void mma16816(float* c, const uint32_t* a, const uint32_t* b) {
    asm volatile("mma.sync.aligned.m16n8k16.row.col.f32.bf16.bf16.f32 "
        "{%0,%1,%2,%3}, {%4,%5,%6,%7}, {%8,%9}, {%0,%1,%2,%3};"
        : "+f"(c[0]), "+f"(c[1]), "+f"(c[2]), "+f"(c[3])
        : "r"(a[0]), "r"(a[1]), "r"(a[2]), "r"(a[3]), "r"(b[0]), "r"(b[1]));
}
#define SWZ(x) ((x) ^ (((x) >> 3) & 0x70))

__device__ __forceinline__ __nv_bfloat162 split_hi(float a, float b) {
    __nv_bfloat162 h; h.x = __float2bfloat16(a); h.y = __float2bfloat16(b); return h;
}
__device__ __forceinline__ __nv_bfloat162 split_lo(float a, float b, __nv_bfloat162 h) {
    __nv_bfloat162 l;
    l.x = __float2bfloat16(a - __bfloat162float(h.x));
    l.y = __float2bfloat16(b - __bfloat162float(h.y));
    return l;
}
__device__ __forceinline__ uint32_t bf2u(__nv_bfloat162 v) {
    return *reinterpret_cast<uint32_t*>(&v);
}

// GRU tile-pair tables (kt-outer)
#define GRU_PNT {0,1,2,3,4,5,6,7,8,9,10,11, 0,1,2,3,4,5,6,7,8,9,10,11, 0,1,2,3,4,5,6,7,12,13,14,15}
#define GRU_PKT {0,0,0,0,0,0,0,0,0,0,0,0,  1,1,1,1,1,1,1,1,1,1,1,1,   2,2,2,2,2,2,2,2,2,2,2,2}

// ================= GRU B matrix value =================
__device__ __forceinline__ float gru_bval(
    int k, int n, const float* Whh, const float* Wih, const float* encW, int KIN)
{
    int blk = n >> 5, j = n & 31;
    if (k < 32) {
        if (blk == 3) return 0.f;
        return Whh[(blk * 32 + j) * 32 + k];
    }
    int f = k - 32;
    if (f >= KIN || blk == 2) return 0.f;
    int row = (blk == 3) ? 64 + j : blk * 32 + j;
    float s = 0.f;
    #pragma unroll
    for (int m = 0; m < 32; m++) s = fmaf(Wih[row * 32 + m], encW[m * KIN + f], s);
    return s;
}

// ====== merged weight prepack: MLP B-fragments + GRU B-fragments/biases =====
__global__ void k_packw(
    const float* __restrict__ W0, const float* __restrict__ W1,
    const float* __restrict__ aWih, const float* __restrict__ aWhh,
    const float* __restrict__ abih, const float* __restrict__ abhh,
    const float* __restrict__ eAW,  const float* __restrict__ eAb,
    const float* __restrict__ mWih, const float* __restrict__ mWhh,
    const float* __restrict__ mbih, const float* __restrict__ mbhh,
    const float* __restrict__ eMW,  const float* __restrict__ eMb)
{
    int tid = blockIdx.x * 256 + threadIdx.x;
    int lane = tid & 31, tq = lane & 3, g = lane >> 2;
    if (tid < 8192) {                       // W0 fragments
        int q = tid >> 5;
        int part = q & 1; q >>= 1;
        int ntg = q & 31;
        int k16 = q >> 5;
        int n = ntg * 8 + g;
        uint32_t rr[2];
        #pragma unroll
        for (int r = 0; r < 2; r++) {
            int k0 = k16 * 16 + tq * 2 + r * 8;
            float v0 = W0[n * 64 + k0], v1 = W0[n * 64 + k0 + 1];
            __nv_bfloat162 hh = split_hi(v0, v1);
            if (part == 0) rr[r] = bf2u(hh);
            else           rr[r] = bf2u(split_lo(v0, v1, hh));
        }
        g_W0f[tid] = make_uint2(rr[0], rr[1]);
    } else if (tid < 40960) {               // W1 fragments
        int j = tid - 8192;
        int q = j >> 5;
        int part = q & 1; q >>= 1;
        int ntg = q & 31;
        int ck = q >> 5;
        int n = ntg * 8 + g;
        uint32_t rr[2];
        #pragma unroll
        for (int r = 0; r < 2; r++) {
            int k0 = ck * 16 + tq * 2 + r * 8;
            float v0 = W1[n * 256 + k0], v1 = W1[n * 256 + k0 + 1];
            __nv_bfloat162 hh = split_hi(v0, v1);
            if (part == 0) rr[r] = bf2u(hh);
            else           rr[r] = bf2u(split_lo(v0, v1, hh));
        }
        g_W1f[j] = make_uint2(rr[0], rr[1]);
    } else if (tid < 40960 + 2304) {        // GRU B fragments
        const int PNT[36] = GRU_PNT;
        const int PKT[36] = GRU_PKT;
        int u = tid - 40960;
        int p = (u >> 5) % 36;
        int ty = u / (36 * 32);
        const float* Whh = ty ? mWhh : aWhh;
        const float* Wih = ty ? mWih : aWih;
        const float* eW  = ty ? eMW  : eAW;
        int KIN = ty ? 4 : 7;
        int n = PNT[p] * 8 + g;
        uint32_t rh[2], rl[2];
        #pragma unroll
        for (int r = 0; r < 2; r++) {
            int k0 = PKT[p] * 16 + tq * 2 + r * 8;
            float v0 = gru_bval(k0,     n, Whh, Wih, eW, KIN);
            float v1 = gru_bval(k0 + 1, n, Whh, Wih, eW, KIN);
            __nv_bfloat162 hh = split_hi(v0, v1);
            __nv_bfloat162 ll = split_lo(v0, v1, hh);
            rh[r] = bf2u(hh); rl[r] = bf2u(ll);
        }
        int base = (ty * 72 + p * 2) * 32 + lane;
        g_gB[base]      = make_uint2(rh[0], rh[1]);
        g_gB[base + 32] = make_uint2(rl[0], rl[1]);
    } else if (tid < 40960 + 2304 + 256) {  // GRU biases
        int u = tid - 40960 - 2304;
        int ty = u >> 7, n = u & 127;
        const float* Wih = ty ? mWih : aWih;
        const float* bih = ty ? mbih : abih;
        const float* bhh = ty ? mbhh : abhh;
        const float* eB  = ty ? eMb  : eAb;
        int blk = n >> 5, j = n & 31;
        float b;
        if (blk == 2) {
            b = bhh[64 + j];
        } else {
            int row = (blk == 3) ? 64 + j : blk * 32 + j;
            float bc = bih[row];
            #pragma unroll
            for (int m = 0; m < 32; m++) bc = fmaf(Wih[row * 32 + m], eB[m], bc);
            b = (blk < 2) ? bc + bhh[row] : bc;
        }
        g_gBias[ty * 128 + n] = b;
    }
}

// X A-fragment prepack (unchanged)
__global__ void k_packg_x(const float* __restrict__ obs) {
    int tid = blockIdx.x * 256 + threadIdx.x;
    int lane = tid & 31;
    int s = tid >> 5;
    int t = s & 127;
    int gr = s >> 7;
    int g = lane >> 2, tq = lane & 3;

    int KIN, xoff;
    int b0;
    if (gr < 128) { KIN = 7; xoff = 8; b0 = gr * 16; }
    else {
        int gi = gr - 128;
        KIN = 4;
        xoff = (gi < 128) ? 0 : 4;
        b0 = (gi < 128) ? gi * 16 : (gi - 128) * 16;
    }
    uint32_t hr[4], lr[4];
    #pragma unroll
    for (int r = 0; r < 4; r++) {
        int row = g + 8 * (r & 1);
        int k0 = tq * 2 + (r >> 1) * 8;
        float v0 = 0.f, v1 = 0.f;
        if (k0 < KIN)
            v0 = obs[(size_t)(b0 + row) * Tq * 15 + t * 15 + xoff + k0];
        if (k0 + 1 < KIN)
            v1 = obs[(size_t)(b0 + row) * Tq * 15 + t * 15 + xoff + k0 + 1];
        __nv_bfloat162 hh = split_hi(v0, v1);
        __nv_bfloat162 ll = split_lo(v0, v1, hh);
        hr[r] = bf2u(hh); lr[r] = bf2u(ll);
    }
    size_t idx = ((size_t)(gr * 128 + t) * 32 + lane) * 2;
    g_gX[idx]     = make_uint4(hr[0], hr[1], hr[2], hr[3]);
    g_gX[idx + 1] = make_uint4(lr[0], lr[1], lr[2], lr[3]);
}

// ====== GRU: tensor-core recurrence (R10 version, verbatim) ======
__global__ void __launch_bounds__(32) k_gru_tc(
    const float* __restrict__ rnn, float* __restrict__ next_h)
{
    const int PNT[36] = GRU_PNT;
    const int PKT[36] = GRU_PKT;
    int lane = threadIdx.x & 31;
    int w = blockIdx.x;
    int g = lane >> 2, tq = lane & 3;

    int ty; float* featb; int ib; bool is_air = (w < 128);
    if (is_air) { ty = 0; featb = g_air; ib = w * 16; }
    else {
        ty = 1;
        int gi = w - 128;
        if (gi < 128) { featb = g_m1; ib = gi * 16; }
        else          { featb = g_m2; ib = (gi - 128) * 16; }
    }
    int gi = w - 128;

    float hv[4][4];
    #pragma unroll
    for (int nt = 0; nt < 4; nt++) {
        int col = nt * 8 + 2 * tq;
        #pragma unroll
        for (int rh = 0; rh < 2; rh++) {
            int row = g + 8 * rh;
            const float* src;
            if (is_air) src = rnn + (size_t)(w * 16 + row) * 96 + col;
            else {
                int i = gi * 16 + row;
                src = rnn + (size_t)(i >> 1) * 96 + 32 + 32 * (i & 1) + col;
            }
            float2 v = *(const float2*)src;
            hv[nt][rh * 2]     = v.x;
            hv[nt][rh * 2 + 1] = v.y;
        }
    }
    float bias[16][2];
    #pragma unroll
    for (int nt = 0; nt < 16; nt++) {
        float2 v = *(const float2*)(g_gBias + ty * 128 + nt * 8 + 2 * tq);
        bias[nt][0] = v.x; bias[nt][1] = v.y;
    }
    uint32_t Ah[2][4], Al[2][4];
    #pragma unroll
    for (int nt = 0; nt < 4; nt++) {
        int kt = nt >> 1;
        __nv_bfloat162 h01 = split_hi(hv[nt][0], hv[nt][1]);
        __nv_bfloat162 l01 = split_lo(hv[nt][0], hv[nt][1], h01);
        __nv_bfloat162 h23 = split_hi(hv[nt][2], hv[nt][3]);
        __nv_bfloat162 l23 = split_lo(hv[nt][2], hv[nt][3], h23);
        int o = (nt & 1) ? 2 : 0;
        Ah[kt][o] = bf2u(h01); Ah[kt][o + 1] = bf2u(h23);
        Al[kt][o] = bf2u(l01); Al[kt][o + 1] = bf2u(l23);
    }

    const uint2* gBb = g_gB + ty * 72 * 32 + lane;
    const uint4* gXb = g_gX + ((size_t)w * 128) * 32 * 2 + lane * 2;
    float* fr0 = featb + (size_t)(ib + g)     * Tq * 32 + 2 * tq;
    float* fr1 = featb + (size_t)(ib + g + 8) * Tq * 32 + 2 * tq;

    uint4 xh_cur = gXb[0], xl_cur = gXb[1];

    #pragma unroll 1
    for (int t = 0; t < Tq; t++) {
        int tn = (t + 1 < Tq) ? t + 1 : t;
        uint4 xh_nxt = gXb[(size_t)tn * 64];
        uint4 xl_nxt = gXb[(size_t)tn * 64 + 1];

        uint32_t Xh[4] = {xh_cur.x, xh_cur.y, xh_cur.z, xh_cur.w};
        uint32_t Xl[4] = {xl_cur.x, xl_cur.y, xl_cur.z, xl_cur.w};
        float C[16][4];
        #pragma unroll
        for (int nt = 0; nt < 16; nt++) {
            C[nt][0] = bias[nt][0]; C[nt][1] = bias[nt][1];
            C[nt][2] = bias[nt][0]; C[nt][3] = bias[nt][1];
        }
        #pragma unroll
        for (int p = 0; p < 36; p++) {
            int nt = PNT[p], kt = PKT[p];
            uint2 bh = gBb[(p * 2) * 32];
            uint2 bl = gBb[(p * 2 + 1) * 32];
            const uint32_t* ah = (kt == 2) ? Xh : Ah[kt];
            const uint32_t* al = (kt == 2) ? Xl : Al[kt];
            mma16816(C[nt], ah, (const uint32_t*)&bh);
            mma16816(C[nt], ah, (const uint32_t*)&bl);
            mma16816(C[nt], al, (const uint32_t*)&bh);
        }
        #pragma unroll
        for (int nt = 0; nt < 4; nt++) {
            #pragma unroll
            for (int j = 0; j < 4; j++) {
                float r = fsig(C[nt][j]);
                float z = fsig(C[nt + 4][j]);
                float n = tanhap(fmaf(r, C[nt + 8][j], C[nt + 12][j]));
                hv[nt][j] = n + z * (hv[nt][j] - n);
            }
            *(float2*)(fr0 + (size_t)t * 32 + nt * 8) = make_float2(hv[nt][0], hv[nt][1]);
            *(float2*)(fr1 + (size_t)t * 32 + nt * 8) = make_float2(hv[nt][2], hv[nt][3]);
            int kt = nt >> 1;
            __nv_bfloat162 h01 = split_hi(hv[nt][0], hv[nt][1]);
            __nv_bfloat162 l01 = split_lo(hv[nt][0], hv[nt][1], h01);
            __nv_bfloat162 h23 = split_hi(hv[nt][2], hv[nt][3]);
            __nv_bfloat162 l23 = split_lo(hv[nt][2], hv[nt][3], h23);
            int o = (nt & 1) ? 2 : 0;
            Ah[kt][o] = bf2u(h01); Ah[kt][o + 1] = bf2u(h23);
            Al[kt][o] = bf2u(l01); Al[kt][o + 1] = bf2u(l23);
        }
        xh_cur = xh_nxt; xl_cur = xl_nxt;
    }
    #pragma unroll
    for (int nt = 0; nt < 4; nt++) {
        int col = nt * 8 + 2 * tq;
        #pragma unroll
        for (int rh = 0; rh < 2; rh++) {
            int row = g + 8 * rh;
            float2 v = make_float2(hv[nt][rh * 2], hv[nt][rh * 2 + 1]);
            float* dst;
            if (is_air) dst = next_h + (size_t)(w * 16 + row) * 96 + col;
            else {
                int i = gi * 16 + row;
                dst = next_h + (size_t)(i >> 1) * 96 + 32 + 32 * (i & 1) + col;
            }
            *(float2*)dst = v;
        }
    }
}

// ================= attention + fusion (unchanged) =================
__global__ void __launch_bounds__(256) k_attn(
    const float* __restrict__ obs,
    const float* __restrict__ Win, const float* __restrict__ bin,
    const float* __restrict__ Wout, const float* __restrict__ bout)
{
    __shared__ float Ws[96 * 32];
    __shared__ float Wo[32 * 32];
    __shared__ float bs[96], bo[32];
    int t = threadIdx.x;
    for (int i = t; i < 96 * 32; i += 256) Ws[i] = Win[i];
    for (int i = t; i < 32 * 32; i += 256) Wo[i] = Wout[i];
    if (t < 96) bs[t] = bin[t];
    if (t < 32) bo[t] = bout[t];
    __syncthreads();

    int warp = blockIdx.x * 8 + (t >> 5);
    int la = t & 31;
    int n = warp * 32 + la;

    float4 A[8], M1[8], M2[8];
    const float4* ap = (const float4*)(g_air + (size_t)n * 32);
    const float4* p1 = (const float4*)(g_m1 + (size_t)n * 32);
    const float4* p2 = (const float4*)(g_m2 + (size_t)n * 32);
    #pragma unroll
    for (int i = 0; i < 8; i++) { A[i] = ap[i]; M1[i] = p1[i]; M2[i] = p2[i]; }

    const float* op = obs + (size_t)n * 15;
    float o0=op[0],o1=op[1],o2=op[2],o3=op[3],o4=op[4],o5=op[5],o6=op[6],o7=op[7];
    const float T1 = 1.001e-5f, T0 = 1e-8f;
    bool mk0 = (fabsf(o0-1.f)<=T1) && (fabsf(o1)<=T0) && (fabsf(o2-1.f)<=T1) && (fabsf(o3)<=T0);
    bool mk1 = (fabsf(o4-1.f)<=T1) && (fabsf(o5)<=T0) && (fabsf(o6-1.f)<=T1) && (fabsf(o7)<=T0);

    float q[32];
    #pragma unroll
    for (int c = 0; c < 32; c++) {
        float2 a = make_float2(bs[c], 0.f);
        const float4* w = (const float4*)(Ws + c * 32);
        #pragma unroll
        for (int k = 0; k < 8; k++) a = dot4_2(A[k], w[k], a);
        q[c] = a.x + a.y;
    }
    float s1[2] = {0.f, 0.f}, s2[2] = {0.f, 0.f};
    #pragma unroll
    for (int c = 0; c < 32; c++) {
        const float4* w = (const float4*)(Ws + (32 + c) * 32);
        float2 k1 = make_float2(bs[32 + c], 0.f), k2 = make_float2(0.f, 0.f);
        #pragma unroll
        for (int k = 0; k < 8; k++) { k1 = dot4_2(M1[k], w[k], k1); k2 = dot4_2(M2[k], w[k], k2); }
        int hh = c >> 4;
        s1[hh] = fmaf(q[c], k1.x + k1.y, s1[hh]);
        s2[hh] = fmaf(q[c], k2.x + k2.y + bs[32 + c], s2[hh]);
    }
    float w1[2], w2[2];
    #pragma unroll
    for (int hh = 0; hh < 2; hh++) {
        float a = s1[hh] * 0.25f + (mk0 ? -1e9f : 0.f);
        float b = s2[hh] * 0.25f + (mk1 ? -1e9f : 0.f);
        float m = fmaxf(a, b);
        float e1 = __expf(a - m), e2 = __expf(b - m);
        float inv = __fdividef(1.0f, e1 + e2);
        w1[hh] = e1 * inv; w2[hh] = e2 * inv;
    }
    float ctx[32];
    #pragma unroll
    for (int c = 0; c < 32; c++) {
        const float4* w = (const float4*)(Ws + (64 + c) * 32);
        float2 v1 = make_float2(bs[64 + c], 0.f), v2 = make_float2(0.f, 0.f);
        #pragma unroll
        for (int k = 0; k < 8; k++) { v1 = dot4_2(M1[k], w[k], v1); v2 = dot4_2(M2[k], w[k], v2); }
        int hh = c >> 4;
        ctx[c] = w1[hh] * (v1.x + v1.y) + w2[hh] * (v2.x + v2.y + bs[64 + c]);
    }
    bool allm = mk0 && mk1;
    float at[32];
    #pragma unroll
    for (int o = 0; o < 32; o++) {
        float2 a = make_float2(bo[o], 0.f);
        const float4* w = (const float4*)(Wo + o * 32);
        #pragma unroll
        for (int c4 = 0; c4 < 8; c4++) {
            float4 cv = make_float4(ctx[4*c4], ctx[4*c4+1], ctx[4*c4+2], ctx[4*c4+3]);
            a = dot4_2(cv, w[c4], a);
        }
        at[o] = allm ? 0.0f : (a.x + a.y);
    }
    float4* fr = (float4*)(g_fusion + (size_t)n * 64);
    #pragma unroll
    for (int i = 0; i < 8; i++) fr[i] = A[i];
    #pragma unroll
    for (int i = 0; i < 8; i++)
        fr[8 + i] = make_float4(at[4*i], at[4*i+1], at[4*i+2], at[4*i+3]);
}

// ======= HMMA MLP: B from global fragments, no smem B path, no loop syncs ===
#define SM_B0  0
#define SM_B1  1024
#define SM_OW  2048
#define SM_A1H 3072
#define SM_A1L 36864
#define SM_RED 70656
#define SM_TOT 72704
#define SM_A0H 3072
#define SM_A0L 11264
#define PA1 528

__global__ void __launch_bounds__(256, 2) k_mlp_h(
    const float* __restrict__ b0, const float* __restrict__ b1,
    const float* __restrict__ oW, const float* __restrict__ ob,
    float* __restrict__ val)
{
    extern __shared__ char smem[];
    uint32_t smb = smem_u32(smem);
    int tid = threadIdx.x, wid = tid >> 5, lane = tid & 31;
    int g = lane >> 2, tq = lane & 3;
    int row0 = blockIdx.x * 64;

    float* b0s = (float*)(smem + SM_B0);
    float* b1s = (float*)(smem + SM_B1);
    float* ows = (float*)(smem + SM_OW);
    b0s[tid] = b0[tid]; b1s[tid] = b1[tid]; ows[tid] = oW[tid];

    int aro = lane & 15;
    int aco = (lane >> 1) & 8;

    // ---- phase A: split fusion tile -> A0h/A0l (swizzled) ----
    {
        const float4* Fg = (const float4*)g_fusion + (size_t)row0 * 16;
        #pragma unroll
        for (int q = 0; q < 4; q++) {
            int id = tid + 256 * q;
            int r = id >> 4, c4 = id & 15;
            float4 v = Fg[id];
            __nv_bfloat162 h0 = split_hi(v.x, v.y), l0 = split_lo(v.x, v.y, h0);
            __nv_bfloat162 h1 = split_hi(v.z, v.w), l1 = split_lo(v.z, v.w, h1);
            uint32_t o0 = SWZ((uint32_t)(r * 128 + c4 * 8));
            uint32_t o1 = SWZ((uint32_t)(r * 128 + c4 * 8 + 4));
            *(__nv_bfloat162*)(smem + SM_A0H + o0) = h0;
            *(__nv_bfloat162*)(smem + SM_A0H + o1) = h1;
            *(__nv_bfloat162*)(smem + SM_A0L + o0) = l0;
            *(__nv_bfloat162*)(smem + SM_A0L + o1) = l1;
        }
    }
    __syncthreads();

    // ---- phase B: layer 0 (k=64), B fragments via LDG ----
    float acc[4][4][4];
    #pragma unroll
    for (int m = 0; m < 4; m++)
        #pragma unroll
        for (int nt = 0; nt < 4; nt++)
            #pragma unroll
            for (int r = 0; r < 4; r++) acc[m][nt][r] = 0.f;
    #pragma unroll 1
    for (int k16 = 0; k16 < 4; k16++) {
        uint2 bh[4], bl[4];
        #pragma unroll
        for (int nt = 0; nt < 4; nt++) {
            int f = ((k16 * 32 + wid * 4 + nt) * 2) * 32 + lane;
            bh[nt] = g_W0f[f];
            bl[nt] = g_W0f[f + 32];
        }
        #pragma unroll
        for (int m = 0; m < 4; m++) {
            uint32_t ah[4], al[4];
            uint32_t aa = SWZ((uint32_t)((m * 16 + aro) * 128 + (k16 * 16 + aco) * 2));
            ldsm4(ah, smb + SM_A0H + aa);
            ldsm4(al, smb + SM_A0L + aa);
            #pragma unroll
            for (int nt = 0; nt < 4; nt++) {
                mma16816(acc[m][nt], ah, (const uint32_t*)&bh[nt]);
                mma16816(acc[m][nt], ah, (const uint32_t*)&bl[nt]);
                mma16816(acc[m][nt], al, (const uint32_t*)&bh[nt]);
            }
        }
    }
    __syncthreads();   // A0 reads done before A1 overwrites region

    // ---- phase C: bias+leaky -> split -> A1h/A1l ----
    #pragma unroll
    for (int m = 0; m < 4; m++)
        #pragma unroll
        for (int nt = 0; nt < 4; nt++) {
            int c0 = wid * 32 + 8 * nt + 2 * tq;
            float v0 = acc[m][nt][0] + b0s[c0];
            float v1 = acc[m][nt][1] + b0s[c0 + 1];
            float v2 = acc[m][nt][2] + b0s[c0];
            float v3 = acc[m][nt][3] + b0s[c0 + 1];
            v0 = v0 > 0.f ? v0 : 0.01f * v0;
            v1 = v1 > 0.f ? v1 : 0.01f * v1;
            v2 = v2 > 0.f ? v2 : 0.01f * v2;
            v3 = v3 > 0.f ? v3 : 0.01f * v3;
            int r0 = 16 * m + g, r1 = r0 + 8;
            __nv_bfloat162 h01 = split_hi(v0, v1), l01 = split_lo(v0, v1, h01);
            __nv_bfloat162 h23 = split_hi(v2, v3), l23 = split_lo(v2, v3, h23);
            *(__nv_bfloat162*)(smem + SM_A1H + r0 * PA1 + c0 * 2) = h01;
            *(__nv_bfloat162*)(smem + SM_A1L + r0 * PA1 + c0 * 2) = l01;
            *(__nv_bfloat162*)(smem + SM_A1H + r1 * PA1 + c0 * 2) = h23;
            *(__nv_bfloat162*)(smem + SM_A1L + r1 * PA1 + c0 * 2) = l23;
        }
    __syncthreads();   // A1 complete; loop below is sync-free

    // ---- phase D: layer 1 (k=256), B fragments via LDG, zero syncs ----
    float a2[4][4][4];
    #pragma unroll
    for (int m = 0; m < 4; m++)
        #pragma unroll
        for (int nt = 0; nt < 4; nt++)
            #pragma unroll
            for (int r = 0; r < 4; r++) a2[m][nt][r] = 0.f;
    #pragma unroll 1
    for (int c = 0; c < 8; c++) {
        #pragma unroll
        for (int k16 = 0; k16 < 2; k16++) {
            uint2 bh[4], bl[4];
            #pragma unroll
            for (int nt = 0; nt < 4; nt++) {
                int f = (((c * 2 + k16) * 32 + wid * 4 + nt) * 2) * 32 + lane;
                bh[nt] = g_W1f[f];
                bl[nt] = g_W1f[f + 32];
            }
            #pragma unroll
            for (int m = 0; m < 4; m++) {
                uint32_t ah[4], al[4];
                uint32_t aa = (uint32_t)((m * 16 + aro) * PA1 + (c * 32 + k16 * 16 + aco) * 2);
                ldsm4(ah, smb + SM_A1H + aa);
                ldsm4(al, smb + SM_A1L + aa);
                #pragma unroll
                for (int nt = 0; nt < 4; nt++) {
                    mma16816(a2[m][nt], ah, (const uint32_t*)&bh[nt]);
                    mma16816(a2[m][nt], ah, (const uint32_t*)&bl[nt]);
                    mma16816(a2[m][nt], al, (const uint32_t*)&bh[nt]);
                }
            }
        }
    }

    // ---- phase E: bias+leaky, dot out_W, reduce ----
    float* red = (float*)(smem + SM_RED);
    float p[4][2];
    #pragma unroll
    for (int m = 0; m < 4; m++) { p[m][0] = 0.f; p[m][1] = 0.f; }
    #pragma unroll
    for (int m = 0; m < 4; m++)
        #pragma unroll
        for (int nt = 0; nt < 4; nt++) {
            int c0 = wid * 32 + 8 * nt + 2 * tq;
            float w0v = ows[c0], w1v = ows[c0 + 1];
            float bb0 = b1s[c0], bb1 = b1s[c0 + 1];
            float v0 = a2[m][nt][0] + bb0;
            float v1 = a2[m][nt][1] + bb1;
            float v2 = a2[m][nt][2] + bb0;
            float v3 = a2[m][nt][3] + bb1;
            v0 = v0 > 0.f ? v0 : 0.01f * v0;
            v1 = v1 > 0.f ? v1 : 0.01f * v1;
            v2 = v2 > 0.f ? v2 : 0.01f * v2;
            v3 = v3 > 0.f ? v3 : 0.01f * v3;
            p[m][0] = fmaf(v0, w0v, p[m][0]);
            p[m][0] = fmaf(v1, w1v, p[m][0]);
            p[m][1] = fmaf(v2, w0v, p[m][1]);
            p[m][1] = fmaf(v3, w1v, p[m][1]);
        }
    #pragma unroll
    for (int off = 1; off <= 2; off <<= 1)
        #pragma unroll
        for (int m = 0; m < 4; m++) {
            p[m][0] += __shfl_xor_sync(0xffffffffu, p[m][0], off);
            p[m][1] += __shfl_xor_sync(0xffffffffu, p[m][1], off);
        }
    if (tq == 0) {
        #pragma unroll
        for (int m = 0; m < 4; m++) {
            red[wid * 64 + 16 * m + g]     = p[m][0];
            red[wid * 64 + 16 * m + g + 8] = p[m][1];
        }
    }
    __syncthreads();
    if (tid < 64) {
        float s = __ldg(ob);
        #pragma unroll
        for (int w8 = 0; w8 < 8; w8++) s += red[w8 * 64 + tid];
        val[row0 + tid] = s;
    }
}

extern "C" void kernel_launch(void* const* d_in, const int* in_sizes, int n_in,
                              void* d_out, int out_size) {
    const float* obs   = (const float*)d_in[0];
    const float* rnn   = (const float*)d_in[1];
    const float* eAW   = (const float*)d_in[2];
    const float* eAb   = (const float*)d_in[3];
    const float* eMW   = (const float*)d_in[4];
    const float* eMb   = (const float*)d_in[5];
    const float* aWih  = (const float*)d_in[6];
    const float* aWhh  = (const float*)d_in[7];
    const float* abih  = (const float*)d_in[8];
    const float* abhh  = (const float*)d_in[9];
    const float* mWih  = (const float*)d_in[10];
    const float* mWhh  = (const float*)d_in[11];
    const float* mbih  = (const float*)d_in[12];
    const float* mbhh  = (const float*)d_in[13];
    const float* Win   = (const float*)d_in[14];
    const float* bin   = (const float*)d_in[15];
    const float* Wout  = (const float*)d_in[16];
    const float* bout  = (const float*)d_in[17];
    const float* W0    = (const float*)d_in[18];
    const float* b0    = (const float*)d_in[19];
    const float* W1    = (const float*)d_in[20];
    const float* b1    = (const float*)d_in[21];
    const float* oW    = (const float*)d_in[22];
    const float* ob    = (const float*)d_in[23];

    float* out_val = (float*)d_out;
    float* out_h   = (float*)d_out + Nq;

    k_packw<<<170, 256>>>(W0, W1, aWih, aWhh, abih, abhh, eAW, eAb,
                          mWih, mWhh, mbih, mbhh, eMW, eMb);
    k_packg_x<<<6144, 256>>>(obs);
    k_gru_tc<<<384, 32>>>(rnn, out_h);
    k_attn<<<Nq / 32 / 8, 256>>>(obs, Win, bin, Wout, bout);
    cudaFuncSetAttribute(k_mlp_h, cudaFuncAttributeMaxDynamicSharedMemorySize, SM_TOT);
    k_mlp_h<<<Nq / 64, 256, SM_TOT>>>(b0, b1, oW, ob, out_val);
}